// round 1
// baseline (speedup 1.0000x reference)
#include <cuda_runtime.h>
#include <math.h>

#define B_   2
#define T_   16
#define BT   32
#define NTOK 2304
#define C_   512
#define C3   1536
#define NH   8
#define DH   64
#define EPS  1e-6f

// ---------------- scratch (device globals; no allocation allowed) ----------------
__device__ float g_qkv[(size_t)BT * NTOK * C3];   // 453 MB: fused QKV of spatial pass
__device__ float g_part[BT * 8 * C_];
__device__ float g_partmm[BT * 8];
__device__ float g_xtime[BT * C_];                // also reused for (temb + t_out)
__device__ float g_mm[BT];
__device__ float g_qkvt[BT * C3];
__device__ float g_tout[BT * C_];
__device__ float g_bias[BT * C3];
__device__ float g_kv[BT * NH * DH * DH];
__device__ float g_ksum[BT * NH * DH];

__device__ __forceinline__ float phi(float x) {
    // elu(x)+1  with alpha=1:  x>0 ? x+1 : exp(x)
    return x > 0.f ? x + 1.f : expf(x);
}

// ---------------- K1: partial frame sums of x and motion ----------------
__global__ void k1_partial(const float* __restrict__ x, const float* __restrict__ motion) {
    int bt = blockIdx.x, chunk = blockIdx.y;
    int c = threadIdx.x;                    // 512 threads
    const int RPC = NTOK / 8;               // 288 rows per chunk
    int n0 = chunk * RPC;
    const float* xp = x + ((size_t)(bt * NTOK + n0)) * C_ + c;
    float s = 0.f;
    for (int r = 0; r < RPC; ++r) s += xp[(size_t)r * C_];
    g_part[(bt * 8 + chunk) * C_ + c] = s;

    __shared__ float sm[512];
    float m = 0.f;
    for (int r = c; r < RPC; r += 512) m += motion[bt * NTOK + n0 + r];
    sm[c] = m;
    __syncthreads();
    for (int off = 256; off > 0; off >>= 1) {
        if (c < off) sm[c] += sm[c + off];
        __syncthreads();
    }
    if (c == 0) g_partmm[bt * 8 + chunk] = sm[0];
}

// ---------------- K2: finalize x_time (+temb) and mm ----------------
__global__ void k2_final(const float* __restrict__ temb) {
    int bt = blockIdx.x, c = threadIdx.x;   // 512 threads
    float s = 0.f;
    for (int j = 0; j < 8; ++j) s += g_part[(bt * 8 + j) * C_ + c];
    g_xtime[bt * C_ + c] = s * (1.f / NTOK) + temb[c];
    if (c == 0) {
        float m = 0.f;
        for (int j = 0; j < 8; ++j) m += g_partmm[bt * 8 + j];
        g_mm[bt] = m * (1.f / NTOK);
    }
}

// ---------------- K3: small vec-mat  dst[bt][col] = dot(g_xtime[bt], W[:,col]) ----------------
__global__ void k3_vecmat(const float* __restrict__ W, int mode) {
    // grid (BT, 6), block 256
    int bt = blockIdx.x;
    int col = blockIdx.y * 256 + threadIdx.x;
    __shared__ float v[C_];
    for (int i = threadIdx.x; i < C_; i += 256) v[i] = g_xtime[bt * C_ + i];
    __syncthreads();
    float s = 0.f;
    #pragma unroll 8
    for (int c = 0; c < C_; ++c) s += v[c] * W[(size_t)c * C3 + col];
    float* dst = mode ? g_bias : g_qkvt;
    dst[bt * C3 + col] = s;
}

// ---------------- K4: temporal linear attention (T=16, per (b,h)) ----------------
__global__ void k4_temporal() {
    // grid (B_, NH), block 64
    int b = blockIdx.x, h = blockIdx.y, e = threadIdx.x;
    __shared__ float q[T_][DH], k[T_][DH], v[T_][DH];
    __shared__ float kvs[DH][DH + 1], ks[DH], mw[T_];
    for (int t = 0; t < T_; ++t) {
        int base = (b * T_ + t) * C3 + h * DH + e;
        q[t][e] = g_qkvt[base];
        k[t][e] = g_qkvt[base + C_];
        v[t][e] = g_qkvt[base + 2 * C_];
    }
    if (e < T_) mw[e] = 1.f + tanhf(g_mm[b * T_ + e]);
    __syncthreads();
    for (int t = 0; t < T_; ++t) {
        q[t][e] = phi(q[t][e]) * mw[t];
        k[t][e] = phi(k[t][e]);
    }
    __syncthreads();
    {   // thread e plays role of d
        float s = 0.f;
        for (int t = 0; t < T_; ++t) s += k[t][e];
        ks[e] = s;
    }
    for (int d = 0; d < DH; ++d) {  // kv column e
        float s = 0.f;
        for (int t = 0; t < T_; ++t) s += k[t][d] * v[t][e];
        kvs[d][e] = s;
    }
    __syncthreads();
    for (int t = 0; t < T_; ++t) {
        float den = 0.f, o = 0.f;
        #pragma unroll
        for (int d = 0; d < DH; ++d) {
            float qd = q[t][d];
            den += qd * ks[d];
            o   += qd * kvs[d][e];
        }
        float z = 1.f / (den + EPS);
        g_tout[(b * T_ + t) * C_ + h * DH + e] = o * z;
    }
}

// ---------------- K5 prep: g_xtime <- temb + t_out (input to K3 mode=1) ----------------
__global__ void k5_prep(const float* __restrict__ temb) {
    int bt = blockIdx.x, c = threadIdx.x;   // 512 threads
    g_xtime[bt * C_ + c] = temb[c] + g_tout[bt * C_ + c];
}

// ---------------- K6: big fp32 GEMM  g_qkv = x @ W + bias[bt] ----------------
// M=73728, K=512, N=1536.  128x128x8 tiles, 256 threads, 8x8 microtiles.
#define GBM 128
#define GBN 128
#define GBK 8
#define ASTR 132   // padded A-tile stride (132*4B = 528B, 16B-aligned, bank-spread)

__global__ __launch_bounds__(256) void k6_gemm(const float* __restrict__ A,
                                               const float* __restrict__ W) {
    __shared__ float As[GBK * ASTR];
    __shared__ float Bs[GBK * GBN];
    int bm = blockIdx.y, bn = blockIdx.x;
    int t = threadIdx.x;
    int ty = t >> 4, tx = t & 15;
    int rowBase = bm * GBM;
    int colBase = bn * GBN;

    float acc[8][8];
    #pragma unroll
    for (int i = 0; i < 8; ++i)
        #pragma unroll
        for (int j = 0; j < 8; ++j) acc[i][j] = 0.f;

    int aRow = t >> 1;            // 0..127
    int aK   = (t & 1) * 4;       // 0 or 4
    int bK   = t >> 5;            // 0..7
    int bCol = (t & 31) * 4;

    const float* Ap = A + (size_t)(rowBase + aRow) * C_ + aK;
    const float* Bp = W + (size_t)bK * C3 + colBase + bCol;

    for (int kk = 0; kk < C_; kk += GBK) {
        float4 a4 = *(const float4*)(Ap + kk);
        As[(aK + 0) * ASTR + aRow] = a4.x;
        As[(aK + 1) * ASTR + aRow] = a4.y;
        As[(aK + 2) * ASTR + aRow] = a4.z;
        As[(aK + 3) * ASTR + aRow] = a4.w;
        *(float4*)(&Bs[bK * GBN + bCol]) = *(const float4*)(Bp + (size_t)kk * C3);
        __syncthreads();
        #pragma unroll
        for (int k = 0; k < GBK; ++k) {
            float4 a0 = *(const float4*)(&As[k * ASTR + ty * 8]);
            float4 a1 = *(const float4*)(&As[k * ASTR + ty * 8 + 4]);
            float4 b0 = *(const float4*)(&Bs[k * GBN + tx * 8]);
            float4 b1 = *(const float4*)(&Bs[k * GBN + tx * 8 + 4]);
            float a[8] = {a0.x, a0.y, a0.z, a0.w, a1.x, a1.y, a1.z, a1.w};
            float b[8] = {b0.x, b0.y, b0.z, b0.w, b1.x, b1.y, b1.z, b1.w};
            #pragma unroll
            for (int i = 0; i < 8; ++i)
                #pragma unroll
                for (int j = 0; j < 8; ++j)
                    acc[i][j] += a[i] * b[j];
        }
        __syncthreads();
    }

    int bt = rowBase / NTOK;   // each 128-row tile lies inside one frame (2304 = 18*128)
    float bv[8];
    #pragma unroll
    for (int j = 0; j < 8; ++j) bv[j] = g_bias[bt * C3 + colBase + tx * 8 + j];
    #pragma unroll
    for (int i = 0; i < 8; ++i) {
        size_t off = (size_t)(rowBase + ty * 8 + i) * C3 + colBase + tx * 8;
        float4 o0 = {acc[i][0] + bv[0], acc[i][1] + bv[1], acc[i][2] + bv[2], acc[i][3] + bv[3]};
        float4 o1 = {acc[i][4] + bv[4], acc[i][5] + bv[5], acc[i][6] + bv[6], acc[i][7] + bv[7]};
        *(float4*)(&g_qkv[off])     = o0;
        *(float4*)(&g_qkv[off + 4]) = o1;
    }
}

// ---------------- K7: per (bt,h) build kv = phi(k)^T v  and ksum ----------------
__global__ __launch_bounds__(256) void k7_kv() {
    int bt = blockIdx.x, h = blockIdx.y;
    int t = threadIdx.x;
    int d = t >> 2;           // 0..63
    int esub = t & 3;         // owns e = esub + 4*j
    __shared__ float ks[16][DH], vs[16][DH];
    float accKV[16];
    #pragma unroll
    for (int j = 0; j < 16; ++j) accKV[j] = 0.f;
    float accS = 0.f;

    const float* base = g_qkv + (size_t)(bt * NTOK) * C3 + h * DH;
    int lrow = t >> 4;          // 0..15
    int lc4  = (t & 15) * 4;    // 0,4,...,60

    for (int n0 = 0; n0 < NTOK; n0 += 16) {
        const float* kp = base + (size_t)(n0 + lrow) * C3 + C_ + lc4;
        float4 k4 = *(const float4*)kp;
        ks[lrow][lc4 + 0] = phi(k4.x);
        ks[lrow][lc4 + 1] = phi(k4.y);
        ks[lrow][lc4 + 2] = phi(k4.z);
        ks[lrow][lc4 + 3] = phi(k4.w);
        const float* vp = base + (size_t)(n0 + lrow) * C3 + 2 * C_ + lc4;
        *(float4*)(&vs[lrow][lc4]) = *(const float4*)vp;
        __syncthreads();
        #pragma unroll
        for (int r = 0; r < 16; ++r) {
            float pk = ks[r][d];
            #pragma unroll
            for (int j = 0; j < 16; ++j)
                accKV[j] += pk * vs[r][esub + 4 * j];
            accS += pk;
        }
        __syncthreads();
    }
    float* kvout = g_kv + ((size_t)(bt * NH + h) * DH + d) * DH;
    #pragma unroll
    for (int j = 0; j < 16; ++j) kvout[esub + 4 * j] = accKV[j];
    if (esub == 0) g_ksum[(bt * NH + h) * DH + d] = accS;
}

// ---------------- K8: apply  out = z * (phi(q)*mw) @ kv ----------------
__global__ __launch_bounds__(256) void k8_apply(const float* __restrict__ motion,
                                                float* __restrict__ out) {
    // grid (BT, NH, 24): 96 tokens per block, 4 tokens in flight (64 thr each)
    int bt = blockIdx.x, h = blockIdx.y, chunk = blockIdx.z;
    int t = threadIdx.x;
    int sub = t >> 6, e = t & 63;
    __shared__ float kvs[DH * DH];
    __shared__ float ks[DH];
    __shared__ float qs[4][DH];
    __shared__ float mws[4];

    const float* kvg = g_kv + (size_t)(bt * NH + h) * DH * DH;
    for (int i = t; i < DH * DH; i += 256) kvs[i] = kvg[i];
    if (t < DH) ks[t] = g_ksum[(bt * NH + h) * DH + t];
    __syncthreads();

    int n0 = chunk * 96;
    for (int g = 0; g < 96; g += 4) {
        int n = n0 + g + sub;
        float qv = g_qkv[(size_t)(bt * NTOK + n) * C3 + h * DH + e];
        if (e == 0) mws[sub] = 1.f + tanhf(motion[bt * NTOK + n]);
        qs[sub][e] = qv;
        __syncthreads();
        float mw = mws[sub];
        qs[sub][e] = phi(qv) * mw;
        __syncthreads();
        float den = 0.f, o = 0.f;
        #pragma unroll
        for (int d = 0; d < DH; ++d) {
            float qd = qs[sub][d];
            den += qd * ks[d];
            o   += qd * kvs[d * DH + e];
        }
        float z = 1.f / (den + EPS);
        out[(size_t)(bt * NTOK + n) * C_ + h * DH + e] = o * z;
        __syncthreads();
    }
}

// ---------------- launch ----------------
extern "C" void kernel_launch(void* const* d_in, const int* in_sizes, int n_in,
                              void* d_out, int out_size) {
    const float* x      = (const float*)d_in[0];
    const float* motion = (const float*)d_in[1];
    const float* W      = (const float*)d_in[2];
    const float* temb   = (const float*)d_in[3];
    float* out = (float*)d_out;

    k1_partial<<<dim3(BT, 8), 512>>>(x, motion);
    k2_final<<<BT, 512>>>(temb);
    k3_vecmat<<<dim3(BT, 6), 256>>>(W, 0);      // qkv_t = x_time @ W
    k4_temporal<<<dim3(B_, NH), 64>>>();
    k5_prep<<<BT, 512>>>(temb);
    k3_vecmat<<<dim3(BT, 6), 256>>>(W, 1);      // bias = (temb + t_out) @ W
    k6_gemm<<<dim3(C3 / GBN, (BT * NTOK) / GBM), 256>>>(x, W);
    k7_kv<<<dim3(BT, NH), 256>>>();
    k8_apply<<<dim3(BT, NH, NTOK / 96), 256>>>(motion, out);
}

// round 3
// speedup vs baseline: 1.6962x; 1.6962x over previous
#include <cuda_runtime.h>
#include <cuda_bf16.h>
#include <math.h>
#include <stdint.h>

#define B_   2
#define T_   16
#define BT   32
#define NTOK 2304
#define C_   512
#define C3   1536
#define NH   8
#define DH   64
#define EPS  1e-6f

#define M_   (BT * NTOK)   // 73728
#define KP   1536          // split K' = 3*512
#define TM   128
#define TN   256
#define TK   64
#define NCHUNK (KP / TK)   // 24

// Feature gate: tcgen05 only exists in the arch-specific (sm_103a) device pass.
// The compute_103 PTX fallback pass compiles the #else body instead.
#if defined(__CUDA_ARCH_FEAT_SM103_ALL) || defined(__CUDA_ARCH_FEAT_SM100_ALL) || \
    (defined(__CUDA_ARCH_SPECIFIC__) && (__CUDA_ARCH_SPECIFIC__ == 1030))
#define HAS_TCGEN05 1
#else
#define HAS_TCGEN05 0
#endif

// ---------------- scratch ----------------
__device__ float g_qkv[(size_t)BT * NTOK * C3];
__device__ __nv_bfloat16 g_A[(size_t)M_ * KP];   // [A_hi | A_lo | A_hi]
__device__ __nv_bfloat16 g_B[(size_t)C3 * KP];   // [W_hi^T | W_hi^T | W_lo^T]
__device__ float g_part[BT * 8 * C_];
__device__ float g_partmm[BT * 8];
__device__ float g_xtime[BT * C_];
__device__ float g_mm[BT];
__device__ float g_qkvt[BT * C3];
__device__ float g_tout[BT * C_];
__device__ float g_bias[BT * C3];
__device__ float g_kv[BT * NH * DH * DH];
__device__ float g_ksum[BT * NH * DH];

__device__ __forceinline__ float phi(float x) {
    return x > 0.f ? x + 1.f : expf(x);
}

// ---------------- ptx helpers (generic, safe on all targets) ----------------
__device__ __forceinline__ uint32_t smem_u32(const void* p) {
    uint32_t a;
    asm("{ .reg .u64 t; cvta.to.shared.u64 t, %1; cvt.u32.u64 %0, t; }" : "=r"(a) : "l"(p));
    return a;
}
__device__ __forceinline__ uint32_t elect_one() {
    uint32_t p;
    asm volatile("{ .reg .pred p; elect.sync _|p, 0xFFFFFFFF; selp.b32 %0, 1, 0, p; }" : "=r"(p));
    return p;
}
static __device__ __forceinline__ uint64_t make_desc(uint32_t addr) {
    const uint64_t base = (uint64_t(2) << 61) | (uint64_t(1) << 46) | (uint64_t(64) << 32) | (uint64_t(1) << 16);
    return base | ((uint64_t)(addr >> 4) & 0x3FFF);
}
__device__ __forceinline__ void mbar_init(uint32_t a, uint32_t cnt) {
    asm volatile("mbarrier.init.shared.b64 [%0], %1;" :: "r"(a), "r"(cnt) : "memory");
}
__device__ __forceinline__ void mbar_inval(uint32_t a) {
    asm volatile("mbarrier.inval.shared.b64 [%0];" :: "r"(a) : "memory");
}
__device__ __forceinline__ void mbar_wait(uint32_t a, uint32_t parity) {
    asm volatile(
        "{\n\t.reg .pred P1;\n\tWL_%=:\n\t"
        "mbarrier.try_wait.parity.acquire.cta.shared::cta.b64 P1, [%0], %1, 0x989680;\n\t"
        "@P1 bra.uni WD_%=;\n\tbra.uni WL_%=;\n\tWD_%=:\n\t}"
        :: "r"(a), "r"(parity) : "memory");
}
__device__ __forceinline__ void fence_async() {
    asm volatile("fence.proxy.async.shared::cta;" ::: "memory");
}

#if HAS_TCGEN05
// ---------------- tcgen05 helpers (sm_103a pass only) ----------------
__device__ __forceinline__ void mma_bf16_ss(uint32_t d, uint64_t ad, uint64_t bd, uint32_t idesc, uint32_t en) {
    asm volatile(
        "{\n\t.reg .pred p;\n\tsetp.ne.u32 p, %4, 0;\n\t"
        "tcgen05.mma.cta_group::1.kind::f16 [%0], %1, %2, %3, {%5, %5, %5, %5}, p;\n\t}"
        :: "r"(d), "l"(ad), "l"(bd), "r"(idesc), "r"(en), "r"(0u) : "memory");
}
__device__ __forceinline__ void tc_commit(uint32_t mbar) {
    asm volatile("tcgen05.commit.cta_group::1.mbarrier::arrive::one.shared::cluster.b64 [%0];"
                 :: "r"(mbar) : "memory");
}
#define TC_ALLOC(sa, n)  asm volatile("tcgen05.alloc.cta_group::1.sync.aligned.shared::cta.b32 [%0], %1;" :: "r"(sa), "r"(n) : "memory")
#define TC_DEALLOC(t, n) asm volatile("tcgen05.dealloc.cta_group::1.sync.aligned.b32 %0, %1;" :: "r"(t), "r"(n))
#define TC_FENCE_AFTER()  asm volatile("tcgen05.fence::after_thread_sync;" ::: "memory")
#define TC_FENCE_BEFORE() asm volatile("tcgen05.fence::before_thread_sync;" ::: "memory")
#define TC_WAIT_LD() asm volatile("tcgen05.wait::ld.sync.aligned;" ::: "memory")
#define LDTM_X32(r, a) \
    asm volatile("tcgen05.ld.sync.aligned.32x32b.x32.b32 " \
        "{%0, %1, %2, %3, %4, %5, %6, %7, %8, %9, %10, %11, %12, %13, %14, %15, " \
        "%16, %17, %18, %19, %20, %21, %22, %23, %24, %25, %26, %27, %28, %29, %30, %31}, [%32];" \
        : "=r"((r)[0]), "=r"((r)[1]), "=r"((r)[2]), "=r"((r)[3]), "=r"((r)[4]), "=r"((r)[5]), "=r"((r)[6]), "=r"((r)[7]), \
          "=r"((r)[8]), "=r"((r)[9]), "=r"((r)[10]), "=r"((r)[11]), "=r"((r)[12]), "=r"((r)[13]), "=r"((r)[14]), "=r"((r)[15]), \
          "=r"((r)[16]), "=r"((r)[17]), "=r"((r)[18]), "=r"((r)[19]), "=r"((r)[20]), "=r"((r)[21]), "=r"((r)[22]), "=r"((r)[23]), \
          "=r"((r)[24]), "=r"((r)[25]), "=r"((r)[26]), "=r"((r)[27]), "=r"((r)[28]), "=r"((r)[29]), "=r"((r)[30]), "=r"((r)[31]) \
        : "r"(a))
#endif

// ---------------- K1: partial frame sums ----------------
__global__ void k1_partial(const float* __restrict__ x, const float* __restrict__ motion) {
    int bt = blockIdx.x, chunk = blockIdx.y;
    int c = threadIdx.x;
    const int RPC = NTOK / 8;
    int n0 = chunk * RPC;
    const float* xp = x + ((size_t)(bt * NTOK + n0)) * C_ + c;
    float s = 0.f;
    for (int r = 0; r < RPC; ++r) s += xp[(size_t)r * C_];
    g_part[(bt * 8 + chunk) * C_ + c] = s;

    __shared__ float sm[512];
    float m = 0.f;
    for (int r = c; r < RPC; r += 512) m += motion[bt * NTOK + n0 + r];
    sm[c] = m;
    __syncthreads();
    for (int off = 256; off > 0; off >>= 1) {
        if (c < off) sm[c] += sm[c + off];
        __syncthreads();
    }
    if (c == 0) g_partmm[bt * 8 + chunk] = sm[0];
}

// ---------------- K2 ----------------
__global__ void k2_final(const float* __restrict__ temb) {
    int bt = blockIdx.x, c = threadIdx.x;
    float s = 0.f;
    for (int j = 0; j < 8; ++j) s += g_part[(bt * 8 + j) * C_ + c];
    g_xtime[bt * C_ + c] = s * (1.f / NTOK) + temb[c];
    if (c == 0) {
        float m = 0.f;
        for (int j = 0; j < 8; ++j) m += g_partmm[bt * 8 + j];
        g_mm[bt] = m * (1.f / NTOK);
    }
}

// ---------------- K3: small vec-mat ----------------
__global__ void k3_vecmat(const float* __restrict__ W, int mode) {
    int bt = blockIdx.x;
    int col = blockIdx.y * 256 + threadIdx.x;
    __shared__ float v[C_];
    for (int i = threadIdx.x; i < C_; i += 256) v[i] = g_xtime[bt * C_ + i];
    __syncthreads();
    float s = 0.f;
    #pragma unroll 8
    for (int c = 0; c < C_; ++c) s += v[c] * W[(size_t)c * C3 + col];
    float* dst = mode ? g_bias : g_qkvt;
    dst[bt * C3 + col] = s;
}

// ---------------- K4: temporal linear attention ----------------
__global__ void k4_temporal() {
    int b = blockIdx.x, h = blockIdx.y, e = threadIdx.x;
    __shared__ float q[T_][DH], k[T_][DH], v[T_][DH];
    __shared__ float kvs[DH][DH + 1], ks[DH], mw[T_];
    for (int t = 0; t < T_; ++t) {
        int base = (b * T_ + t) * C3 + h * DH + e;
        q[t][e] = g_qkvt[base];
        k[t][e] = g_qkvt[base + C_];
        v[t][e] = g_qkvt[base + 2 * C_];
    }
    if (e < T_) mw[e] = 1.f + tanhf(g_mm[b * T_ + e]);
    __syncthreads();
    for (int t = 0; t < T_; ++t) {
        q[t][e] = phi(q[t][e]) * mw[t];
        k[t][e] = phi(k[t][e]);
    }
    __syncthreads();
    {
        float s = 0.f;
        for (int t = 0; t < T_; ++t) s += k[t][e];
        ks[e] = s;
    }
    for (int d = 0; d < DH; ++d) {
        float s = 0.f;
        for (int t = 0; t < T_; ++t) s += k[t][d] * v[t][e];
        kvs[d][e] = s;
    }
    __syncthreads();
    for (int t = 0; t < T_; ++t) {
        float den = 0.f, o = 0.f;
        #pragma unroll
        for (int d = 0; d < DH; ++d) {
            float qd = q[t][d];
            den += qd * ks[d];
            o   += qd * kvs[d][e];
        }
        float z = 1.f / (den + EPS);
        g_tout[(b * T_ + t) * C_ + h * DH + e] = o * z;
    }
}

// ---------------- K5 prep ----------------
__global__ void k5_prep(const float* __restrict__ temb) {
    int bt = blockIdx.x, c = threadIdx.x;
    g_xtime[bt * C_ + c] = temb[c] + g_tout[bt * C_ + c];
}

// ---------------- KA: build split-A  [hi | lo | hi] ----------------
__global__ void kA_split(const float* __restrict__ x) {
    size_t idx = (size_t)blockIdx.x * 256 + threadIdx.x;
    size_t row = idx >> 7;
    int q = (int)(idx & 127);
    float4 v = *(const float4*)(x + (row << 9) + q * 4);
    float f[4] = {v.x, v.y, v.z, v.w};
    uint32_t ph[2], pl[2];
    #pragma unroll
    for (int p = 0; p < 2; ++p) {
        __nv_bfloat16 h0 = __float2bfloat16_rn(f[2 * p]);
        __nv_bfloat16 h1 = __float2bfloat16_rn(f[2 * p + 1]);
        __nv_bfloat16 l0 = __float2bfloat16_rn(f[2 * p] - __bfloat162float(h0));
        __nv_bfloat16 l1 = __float2bfloat16_rn(f[2 * p + 1] - __bfloat162float(h1));
        ph[p] = (uint32_t)__bfloat16_as_ushort(h0) | ((uint32_t)__bfloat16_as_ushort(h1) << 16);
        pl[p] = (uint32_t)__bfloat16_as_ushort(l0) | ((uint32_t)__bfloat16_as_ushort(l1) << 16);
    }
    uint2 hv = {ph[0], ph[1]}, lv = {pl[0], pl[1]};
    __nv_bfloat16* base = g_A + row * KP + q * 4;
    *(uint2*)(base)        = hv;
    *(uint2*)(base + 512)  = lv;
    *(uint2*)(base + 1024) = hv;
}

// ---------------- KB: build split-B (transposed W)  [hi | hi | lo] ----------------
__global__ void kB_build(const float* __restrict__ W) {
    int n = blockIdx.x * 256 + threadIdx.x;
    int k = blockIdx.y;
    float w = W[(size_t)k * C3 + n];
    __nv_bfloat16 hi = __float2bfloat16_rn(w);
    __nv_bfloat16 lo = __float2bfloat16_rn(w - __bfloat162float(hi));
    g_B[(size_t)n * KP + k]        = hi;
    g_B[(size_t)n * KP + 512 + k]  = hi;
    g_B[(size_t)n * KP + 1024 + k] = lo;
}

// ---------------- K6: tcgen05 bf16 GEMM  g_qkv = Abig @ Bbig^T + bias ----------------
#define SM_A    0            // 2 x 16384
#define SM_B    32768        // 2 x 32768
#define SM_BIAS 98304        // 1024
#define SM_TPTR 99328
#define SM_MBAR 99336        // 2 x 8
#define SM_SZ   99360

__global__ void __launch_bounds__(128, 2) k6_mma() {
#if HAS_TCGEN05
    extern __shared__ char smem[];
    uint32_t sb = smem_u32(smem);
    int tid = threadIdx.x;
    int bn = blockIdx.x, bm = blockIdx.y;
    int rowBase = bm * TM, colBase = bn * TN;
    int bt = rowBase / NTOK;

    for (int i = tid; i < TN; i += 128)
        ((float*)(smem + SM_BIAS))[i] = g_bias[bt * C3 + colBase + i];

    if (tid < 32) TC_ALLOC(sb + SM_TPTR, 256);
    if (tid == 0) { mbar_init(sb + SM_MBAR, 1); mbar_init(sb + SM_MBAR + 8, 1); }
    __syncthreads();
    uint32_t tmem;
    asm volatile("ld.shared.b32 %0, [%1];" : "=r"(tmem) : "r"(sb + SM_TPTR));

    const uint32_t idesc = (1u << 4) | (1u << 7) | (1u << 10) | (16u << 17) | (8u << 24);

    for (int c = 0; c < NCHUNK; ++c) {
        int s = c & 1;
        if (c >= 2) mbar_wait(sb + SM_MBAR + 8 * s, ((c >> 1) - 1) & 1);

        // A tile: 128 rows x 64 K (bf16) -> SW128 swizzled
        const uint4* Ag = (const uint4*)(g_A + (size_t)rowBase * KP + c * TK);
        char* As = smem + SM_A + s * 16384;
        #pragma unroll
        for (int i = 0; i < 8; ++i) {
            int idx = tid + i * 128;
            int row = idx >> 3, q = idx & 7;
            uint4 v = Ag[(size_t)row * 192 + q];     // row stride = 1536 bf16 = 192 uint4
            uint32_t bo = row * 128 + q * 16;
            *(uint4*)(As + (bo ^ ((bo >> 3) & 0x70))) = v;
        }
        // B tile: 256 rows x 64 K
        const uint4* Bg = (const uint4*)(g_B + (size_t)colBase * KP + c * TK);
        char* Bs = smem + SM_B + s * 32768;
        #pragma unroll
        for (int i = 0; i < 16; ++i) {
            int idx = tid + i * 128;
            int row = idx >> 3, q = idx & 7;
            uint4 v = Bg[(size_t)row * 192 + q];
            uint32_t bo = row * 128 + q * 16;
            *(uint4*)(Bs + (bo ^ ((bo >> 3) & 0x70))) = v;
        }
        __syncthreads();

        if (tid < 32 && elect_one()) {
            fence_async();
            uint64_t ad  = make_desc(sb + SM_A + s * 16384);
            uint64_t bd0 = make_desc(sb + SM_B + s * 32768);
            uint64_t bd1 = bd0 + 1024;               // +16384 bytes: B rows 128..255
            #pragma unroll
            for (int ks = 0; ks < 4; ++ks) {
                uint32_t en = (c > 0 || ks > 0) ? 1u : 0u;
                mma_bf16_ss(tmem,       ad + 2 * ks, bd0 + 2 * ks, idesc, en);
                mma_bf16_ss(tmem + 128, ad + 2 * ks, bd1 + 2 * ks, idesc, en);
            }
            tc_commit(sb + SM_MBAR + 8 * s);
        }
    }

    // drain: each stage committed 12 times -> wait 12th completion (parity 1)
    mbar_wait(sb + SM_MBAR + 0, 1);
    mbar_wait(sb + SM_MBAR + 8, 1);
    TC_FENCE_AFTER();

    int lane = tid & 31, w = tid >> 5;
    size_t orow = (size_t)(rowBase + w * 32 + lane) * C3 + colBase;
    const float* bsm = (const float*)(smem + SM_BIAS);
    for (int b = 0; b < 8; ++b) {
        uint32_t r[32];
        LDTM_X32(r, tmem + b * 32);
        TC_WAIT_LD();
        #pragma unroll
        for (int j = 0; j < 32; j += 4) {
            float4 o;
            o.x = __uint_as_float(r[j + 0]) + bsm[b * 32 + j + 0];
            o.y = __uint_as_float(r[j + 1]) + bsm[b * 32 + j + 1];
            o.z = __uint_as_float(r[j + 2]) + bsm[b * 32 + j + 2];
            o.w = __uint_as_float(r[j + 3]) + bsm[b * 32 + j + 3];
            *(float4*)(g_qkv + orow + b * 32 + j) = o;
        }
    }
    TC_FENCE_BEFORE();
    __syncthreads();
    if (tid == 0) { mbar_inval(sb + SM_MBAR); mbar_inval(sb + SM_MBAR + 8); }
    __syncthreads();
    if (tid < 32) TC_DEALLOC(tmem, 256);
#else
    // Fallback body for the compute_103 PTX pass (never executed on GB300:
    // the sm_103a cubin is always preferred). Slow but correct.
    int tid = threadIdx.x;
    int bn = blockIdx.x, bm = blockIdx.y;
    int rowBase = bm * TM, colBase = bn * TN;
    int bt = rowBase / NTOK;
    for (int e = tid; e < TM * TN; e += 128) {
        int i = e / TN, j = e % TN;
        const __nv_bfloat16* a = g_A + (size_t)(rowBase + i) * KP;
        const __nv_bfloat16* b = g_B + (size_t)(colBase + j) * KP;
        float s = 0.f;
        for (int k = 0; k < KP; ++k)
            s += __bfloat162float(a[k]) * __bfloat162float(b[k]);
        g_qkv[(size_t)(rowBase + i) * C3 + colBase + j] = s + g_bias[bt * C3 + colBase + j];
    }
#endif
}

// ---------------- K7: kv = phi(k)^T v, ksum ----------------
__global__ __launch_bounds__(256) void k7_kv() {
    int bt = blockIdx.x, h = blockIdx.y;
    int t = threadIdx.x;
    int d = t >> 2;
    int esub = t & 3;
    __shared__ float ks[16][DH], vs[16][DH];
    float accKV[16];
    #pragma unroll
    for (int j = 0; j < 16; ++j) accKV[j] = 0.f;
    float accS = 0.f;

    const float* base = g_qkv + (size_t)(bt * NTOK) * C3 + h * DH;
    int lrow = t >> 4;
    int lc4  = (t & 15) * 4;

    for (int n0 = 0; n0 < NTOK; n0 += 16) {
        const float* kp = base + (size_t)(n0 + lrow) * C3 + C_ + lc4;
        float4 k4 = *(const float4*)kp;
        ks[lrow][lc4 + 0] = phi(k4.x);
        ks[lrow][lc4 + 1] = phi(k4.y);
        ks[lrow][lc4 + 2] = phi(k4.z);
        ks[lrow][lc4 + 3] = phi(k4.w);
        const float* vp = base + (size_t)(n0 + lrow) * C3 + 2 * C_ + lc4;
        *(float4*)(&vs[lrow][lc4]) = *(const float4*)vp;
        __syncthreads();
        #pragma unroll
        for (int r = 0; r < 16; ++r) {
            float pk = ks[r][d];
            #pragma unroll
            for (int j = 0; j < 16; ++j)
                accKV[j] += pk * vs[r][esub + 4 * j];
            accS += pk;
        }
        __syncthreads();
    }
    float* kvout = g_kv + ((size_t)(bt * NH + h) * DH + d) * DH;
    #pragma unroll
    for (int j = 0; j < 16; ++j) kvout[esub + 4 * j] = accKV[j];
    if (esub == 0) g_ksum[(bt * NH + h) * DH + d] = accS;
}

// ---------------- K8: out = z * (phi(q)*mw) @ kv ----------------
__global__ __launch_bounds__(256) void k8_apply(const float* __restrict__ motion,
                                                float* __restrict__ out) {
    int bt = blockIdx.x, h = blockIdx.y, chunk = blockIdx.z;
    int t = threadIdx.x;
    int sub = t >> 6, e = t & 63;
    __shared__ float kvs[DH * DH];
    __shared__ float ks[DH];
    __shared__ float qs[4][DH];
    __shared__ float mws[4];

    const float* kvg = g_kv + (size_t)(bt * NH + h) * DH * DH;
    for (int i = t; i < DH * DH; i += 256) kvs[i] = kvg[i];
    if (t < DH) ks[t] = g_ksum[(bt * NH + h) * DH + t];
    __syncthreads();

    int n0 = chunk * 96;
    for (int g = 0; g < 96; g += 4) {
        int n = n0 + g + sub;
        float qv = g_qkv[(size_t)(bt * NTOK + n) * C3 + h * DH + e];
        if (e == 0) mws[sub] = 1.f + tanhf(motion[bt * NTOK + n]);
        qs[sub][e] = qv;
        __syncthreads();
        float mw = mws[sub];
        qs[sub][e] = phi(qv) * mw;
        __syncthreads();
        float den = 0.f, o = 0.f;
        #pragma unroll
        for (int d = 0; d < DH; ++d) {
            float qd = qs[sub][d];
            den += qd * ks[d];
            o   += qd * kvs[d * DH + e];
        }
        float z = 1.f / (den + EPS);
        out[(size_t)(bt * NTOK + n) * C_ + h * DH + e] = o * z;
        __syncthreads();
    }
}

// ---------------- launch ----------------
extern "C" void kernel_launch(void* const* d_in, const int* in_sizes, int n_in,
                              void* d_out, int out_size) {
    const float* x      = (const float*)d_in[0];
    const float* motion = (const float*)d_in[1];
    const float* W      = (const float*)d_in[2];
    const float* temb   = (const float*)d_in[3];
    float* out = (float*)d_out;

    cudaFuncSetAttribute(k6_mma, cudaFuncAttributeMaxDynamicSharedMemorySize, SM_SZ);

    kA_split<<<(int)(((size_t)M_ * 128) / 256), 256>>>(x);
    kB_build<<<dim3(C3 / 256, C_), 256>>>(W);
    k1_partial<<<dim3(BT, 8), 512>>>(x, motion);
    k2_final<<<BT, 512>>>(temb);
    k3_vecmat<<<dim3(BT, 6), 256>>>(W, 0);
    k4_temporal<<<dim3(B_, NH), 64>>>();
    k5_prep<<<BT, 512>>>(temb);
    k3_vecmat<<<dim3(BT, 6), 256>>>(W, 1);
    k6_mma<<<dim3(C3 / TN, M_ / TM), 128, SM_SZ>>>();
    k7_kv<<<dim3(BT, NH), 256>>>();
    k8_apply<<<dim3(BT, NH, NTOK / 96), 256>>>(motion, out);
}

// round 5
// speedup vs baseline: 1.9810x; 1.1679x over previous
#include <cuda_runtime.h>
#include <cuda_bf16.h>
#include <math.h>
#include <stdint.h>

#define B_   2
#define T_   16
#define BT   32
#define NTOK 2304
#define C_   512
#define C3   1536
#define NH   8
#define DH   64
#define EPS  1e-6f

#define M_   (BT * NTOK)   // 73728
#define TM   128
#define TN   256
#define TK   64
#define NCHUNK 24          // K' = 1536 = 24 * 64
#define NBM   (M_ / TM)    // 576
#define NBN   (C3 / TN)    // 6
#define A_TILE_B 16384     // 128 x 64 bf16 swizzled
#define B_TILE_B 32768     // 256 x 64 bf16 swizzled

#if defined(__CUDA_ARCH_FEAT_SM103_ALL) || defined(__CUDA_ARCH_FEAT_SM100_ALL) || \
    (defined(__CUDA_ARCH_SPECIFIC__) && (__CUDA_ARCH_SPECIFIC__ == 1030))
#define HAS_TCGEN05 1
#else
#define HAS_TCGEN05 0
#endif

// ---------------- scratch ----------------
__device__ float g_qkv[(size_t)BT * NTOK * C3];
__device__ __nv_bfloat16 g_At[(size_t)NBM * 16 * (A_TILE_B / 2)];  // [bm][tile 0-7 hi, 8-15 lo]
__device__ __nv_bfloat16 g_Bt[(size_t)NBN * 16 * (B_TILE_B / 2)];  // [bn][tile 0-7 hi, 8-15 lo]
__device__ float g_part[BT * 8 * C_];
__device__ float g_partmm[BT * 8];
__device__ float g_xtime[BT * C_];
__device__ float g_mm[BT];
__device__ float g_qkvt[BT * C3];
__device__ float g_tout[BT * C_];
__device__ float g_bias[BT * C3];
__device__ float g_kv[BT * NH * DH * DH];
__device__ float g_ksum[BT * NH * DH];

__device__ __forceinline__ float phi(float x) {
    return x > 0.f ? x + 1.f : expf(x);
}

// ---------------- ptx helpers (generic) ----------------
__device__ __forceinline__ uint32_t smem_u32(const void* p) {
    uint32_t a;
    asm("{ .reg .u64 t; cvta.to.shared.u64 t, %1; cvt.u32.u64 %0, t; }" : "=r"(a) : "l"(p));
    return a;
}
static __device__ __forceinline__ uint64_t make_desc(uint32_t addr) {
    const uint64_t base = (uint64_t(2) << 61) | (uint64_t(1) << 46) | (uint64_t(64) << 32) | (uint64_t(1) << 16);
    return base | ((uint64_t)(addr >> 4) & 0x3FFF);
}
__device__ __forceinline__ void mbar_init(uint32_t a, uint32_t cnt) {
    asm volatile("mbarrier.init.shared.b64 [%0], %1;" :: "r"(a), "r"(cnt) : "memory");
}
__device__ __forceinline__ void mbar_inval(uint32_t a) {
    asm volatile("mbarrier.inval.shared.b64 [%0];" :: "r"(a) : "memory");
}
__device__ __forceinline__ void mbar_wait(uint32_t a, uint32_t parity) {
    asm volatile(
        "{\n\t.reg .pred P1;\n\tWL_%=:\n\t"
        "mbarrier.try_wait.parity.acquire.cta.shared::cta.b64 P1, [%0], %1, 0x989680;\n\t"
        "@P1 bra.uni WD_%=;\n\tbra.uni WL_%=;\n\tWD_%=:\n\t}"
        :: "r"(a), "r"(parity) : "memory");
}
__device__ __forceinline__ void mbar_expect_tx(uint32_t a, uint32_t bytes) {
    asm volatile("mbarrier.arrive.expect_tx.shared.b64 _, [%0], %1;"
                 :: "r"(a), "r"(bytes) : "memory");
}
__device__ __forceinline__ void bulk_g2s(uint32_t dst, const void* src, uint32_t bytes, uint32_t mbar) {
    asm volatile("cp.async.bulk.shared::cta.global.mbarrier::complete_tx::bytes [%0], [%1], %2, [%3];"
                 :: "r"(dst), "l"(src), "r"(bytes), "r"(mbar) : "memory");
}

#if HAS_TCGEN05
__device__ __forceinline__ void mma_bf16_ss(uint32_t d, uint64_t ad, uint64_t bd, uint32_t idesc, uint32_t en) {
    asm volatile(
        "{\n\t.reg .pred p;\n\tsetp.ne.u32 p, %4, 0;\n\t"
        "tcgen05.mma.cta_group::1.kind::f16 [%0], %1, %2, %3, {%5, %5, %5, %5}, p;\n\t}"
        :: "r"(d), "l"(ad), "l"(bd), "r"(idesc), "r"(en), "r"(0u) : "memory");
}
__device__ __forceinline__ void tc_commit(uint32_t mbar) {
    asm volatile("tcgen05.commit.cta_group::1.mbarrier::arrive::one.shared::cluster.b64 [%0];"
                 :: "r"(mbar) : "memory");
}
#define TC_ALLOC(sa, n)  asm volatile("tcgen05.alloc.cta_group::1.sync.aligned.shared::cta.b32 [%0], %1;" :: "r"(sa), "r"(n) : "memory")
#define TC_DEALLOC(t, n) asm volatile("tcgen05.dealloc.cta_group::1.sync.aligned.b32 %0, %1;" :: "r"(t), "r"(n))
#define TC_FENCE_AFTER()  asm volatile("tcgen05.fence::after_thread_sync;" ::: "memory")
#define TC_FENCE_BEFORE() asm volatile("tcgen05.fence::before_thread_sync;" ::: "memory")
#define TC_WAIT_LD() asm volatile("tcgen05.wait::ld.sync.aligned;" ::: "memory")
#define LDTM_X32(r, a) \
    asm volatile("tcgen05.ld.sync.aligned.32x32b.x32.b32 " \
        "{%0, %1, %2, %3, %4, %5, %6, %7, %8, %9, %10, %11, %12, %13, %14, %15, " \
        "%16, %17, %18, %19, %20, %21, %22, %23, %24, %25, %26, %27, %28, %29, %30, %31}, [%32];" \
        : "=r"((r)[0]), "=r"((r)[1]), "=r"((r)[2]), "=r"((r)[3]), "=r"((r)[4]), "=r"((r)[5]), "=r"((r)[6]), "=r"((r)[7]), \
          "=r"((r)[8]), "=r"((r)[9]), "=r"((r)[10]), "=r"((r)[11]), "=r"((r)[12]), "=r"((r)[13]), "=r"((r)[14]), "=r"((r)[15]), \
          "=r"((r)[16]), "=r"((r)[17]), "=r"((r)[18]), "=r"((r)[19]), "=r"((r)[20]), "=r"((r)[21]), "=r"((r)[22]), "=r"((r)[23]), \
          "=r"((r)[24]), "=r"((r)[25]), "=r"((r)[26]), "=r"((r)[27]), "=r"((r)[28]), "=r"((r)[29]), "=r"((r)[30]), "=r"((r)[31]) \
        : "r"(a))
#endif

// ---------------- K1: partial frame sums ----------------
__global__ void k1_partial(const float* __restrict__ x, const float* __restrict__ motion) {
    int bt = blockIdx.x, chunk = blockIdx.y;
    int c = threadIdx.x;
    const int RPC = NTOK / 8;
    int n0 = chunk * RPC;
    const float* xp = x + ((size_t)(bt * NTOK + n0)) * C_ + c;
    float s = 0.f;
    for (int r = 0; r < RPC; ++r) s += xp[(size_t)r * C_];
    g_part[(bt * 8 + chunk) * C_ + c] = s;

    __shared__ float sm[512];
    float m = 0.f;
    for (int r = c; r < RPC; r += 512) m += motion[bt * NTOK + n0 + r];
    sm[c] = m;
    __syncthreads();
    for (int off = 256; off > 0; off >>= 1) {
        if (c < off) sm[c] += sm[c + off];
        __syncthreads();
    }
    if (c == 0) g_partmm[bt * 8 + chunk] = sm[0];
}

// ---------------- K2 ----------------
__global__ void k2_final(const float* __restrict__ temb) {
    int bt = blockIdx.x, c = threadIdx.x;
    float s = 0.f;
    for (int j = 0; j < 8; ++j) s += g_part[(bt * 8 + j) * C_ + c];
    g_xtime[bt * C_ + c] = s * (1.f / NTOK) + temb[c];
    if (c == 0) {
        float m = 0.f;
        for (int j = 0; j < 8; ++j) m += g_partmm[bt * 8 + j];
        g_mm[bt] = m * (1.f / NTOK);
    }
}

// ---------------- K3: small vec-mat ----------------
__global__ void k3_vecmat(const float* __restrict__ W, int mode) {
    int bt = blockIdx.x;
    int col = blockIdx.y * 256 + threadIdx.x;
    __shared__ float v[C_];
    for (int i = threadIdx.x; i < C_; i += 256) v[i] = g_xtime[bt * C_ + i];
    __syncthreads();
    float s = 0.f;
    #pragma unroll 8
    for (int c = 0; c < C_; ++c) s += v[c] * W[(size_t)c * C3 + col];
    float* dst = mode ? g_bias : g_qkvt;
    dst[bt * C3 + col] = s;
}

// ---------------- K4: temporal linear attention ----------------
__global__ void k4_temporal() {
    int b = blockIdx.x, h = blockIdx.y, e = threadIdx.x;
    __shared__ float q[T_][DH], k[T_][DH], v[T_][DH];
    __shared__ float kvs[DH][DH + 1], ks[DH], mw[T_];
    for (int t = 0; t < T_; ++t) {
        int base = (b * T_ + t) * C3 + h * DH + e;
        q[t][e] = g_qkvt[base];
        k[t][e] = g_qkvt[base + C_];
        v[t][e] = g_qkvt[base + 2 * C_];
    }
    if (e < T_) mw[e] = 1.f + tanhf(g_mm[b * T_ + e]);
    __syncthreads();
    for (int t = 0; t < T_; ++t) {
        q[t][e] = phi(q[t][e]) * mw[t];
        k[t][e] = phi(k[t][e]);
    }
    __syncthreads();
    {
        float s = 0.f;
        for (int t = 0; t < T_; ++t) s += k[t][e];
        ks[e] = s;
    }
    for (int d = 0; d < DH; ++d) {
        float s = 0.f;
        for (int t = 0; t < T_; ++t) s += k[t][d] * v[t][e];
        kvs[d][e] = s;
    }
    __syncthreads();
    for (int t = 0; t < T_; ++t) {
        float den = 0.f, o = 0.f;
        #pragma unroll
        for (int d = 0; d < DH; ++d) {
            float qd = q[t][d];
            den += qd * ks[d];
            o   += qd * kvs[d][e];
        }
        float z = 1.f / (den + EPS);
        g_tout[(b * T_ + t) * C_ + h * DH + e] = o * z;
    }
}

// ---------------- K5 prep ----------------
__global__ void k5_prep(const float* __restrict__ temb) {
    int bt = blockIdx.x, c = threadIdx.x;
    g_xtime[bt * C_ + c] = temb[c] + g_tout[bt * C_ + c];
}

// ---------------- KA: pre-swizzled tile-contiguous split-A ----------------
__global__ void kA_split(const float* __restrict__ x) {
    size_t idx = (size_t)blockIdx.x * 256 + threadIdx.x;
    size_t row = idx >> 7;
    int q = (int)(idx & 127);
    float4 v = *(const float4*)(x + (row << 9) + q * 4);
    float f[4] = {v.x, v.y, v.z, v.w};
    uint32_t ph[2], pl[2];
    #pragma unroll
    for (int p = 0; p < 2; ++p) {
        __nv_bfloat16 h0 = __float2bfloat16_rn(f[2 * p]);
        __nv_bfloat16 h1 = __float2bfloat16_rn(f[2 * p + 1]);
        __nv_bfloat16 l0 = __float2bfloat16_rn(f[2 * p] - __bfloat162float(h0));
        __nv_bfloat16 l1 = __float2bfloat16_rn(f[2 * p + 1] - __bfloat162float(h1));
        ph[p] = (uint32_t)__bfloat16_as_ushort(h0) | ((uint32_t)__bfloat16_as_ushort(h1) << 16);
        pl[p] = (uint32_t)__bfloat16_as_ushort(l0) | ((uint32_t)__bfloat16_as_ushort(l1) << 16);
    }
    uint2 hv = {ph[0], ph[1]}, lv = {pl[0], pl[1]};

    int bm = (int)(row >> 7);
    int lr = (int)(row & 127);
    int ch = q >> 4;
    uint32_t off = (uint32_t)lr * 128 + (uint32_t)(q & 15) * 8;
    uint32_t so = off ^ ((off >> 3) & 0x70);
    char* hiDst = (char*)g_At + ((size_t)(bm * 16 + ch)) * A_TILE_B + so;
    *(uint2*)hiDst = hv;
    *(uint2*)(hiDst + 8 * A_TILE_B) = lv;
}

// ---------------- KB: pre-swizzled tile-contiguous split-B ----------------
__global__ void kB_build(const float* __restrict__ W) {
    int n = blockIdx.x * 256 + threadIdx.x;
    int k = blockIdx.y;
    float w = W[(size_t)k * C3 + n];
    __nv_bfloat16 hi = __float2bfloat16_rn(w);
    __nv_bfloat16 lo = __float2bfloat16_rn(w - __bfloat162float(hi));
    int bn = n >> 8, rt = n & 255, ch = k >> 6, col = k & 63;
    uint32_t off = (uint32_t)rt * 128 + (uint32_t)col * 2;
    uint32_t so = off ^ ((off >> 3) & 0x70);
    char* dst = (char*)g_Bt + ((size_t)(bn * 16 + ch)) * B_TILE_B + so;
    *(__nv_bfloat16*)dst = hi;
    *(__nv_bfloat16*)(dst + 8 * B_TILE_B) = lo;
}

// ---------------- K6: bulk-async-fed tcgen05 bf16 GEMM ----------------
#define SM_A    0            // 2 x 16384
#define SM_B    32768        // 2 x 32768
#define SM_BIAS 98304        // 1024
#define SM_TPTR 99328
#define SM_FULL 99336        // 2 x 8
#define SM_DONE 99352        // 2 x 8
#define SM_SZ   99368

__global__ void __launch_bounds__(128, 2) k6_mma() {
#if HAS_TCGEN05
    extern __shared__ char smem[];
    uint32_t sb = smem_u32(smem);
    int tid = threadIdx.x;
    int bn = blockIdx.x, bm = blockIdx.y;
    int rowBase = bm * TM, colBase = bn * TN;
    int bt = rowBase / NTOK;

    for (int i = tid; i < TN; i += 128)
        ((float*)(smem + SM_BIAS))[i] = g_bias[bt * C3 + colBase + i];

    if (tid < 32) TC_ALLOC(sb + SM_TPTR, 256);
    if (tid == 0) {
        mbar_init(sb + SM_FULL, 1);     mbar_init(sb + SM_FULL + 8, 1);
        mbar_init(sb + SM_DONE, 1);     mbar_init(sb + SM_DONE + 8, 1);
    }
    __syncthreads();
    uint32_t tmem;
    asm volatile("ld.shared.b32 %0, [%1];" : "=r"(tmem) : "r"(sb + SM_TPTR));

    const uint32_t idesc = (1u << 4) | (1u << 7) | (1u << 10) | (16u << 17) | (8u << 24);

    if (tid == 0) {
        const char* Abase = (const char*)g_At + (size_t)bm * 16 * A_TILE_B;
        const char* Bbase = (const char*)g_Bt + (size_t)bn * 16 * B_TILE_B;
        for (int c = 0; c < NCHUNK; ++c) {
            int s = c & 1;
            int ph = c >> 1;
            if (c >= 2) mbar_wait(sb + SM_DONE + 8 * s, (ph - 1) & 1);

            int at = c & 15;                       // A: 0-7 hi, 8-15 lo, then hi again
            int btile = (c < 8) ? c : (c - 8);     // B: hi, hi, lo
            uint32_t fullb = sb + SM_FULL + 8 * s;
            mbar_expect_tx(fullb, A_TILE_B + B_TILE_B);
            bulk_g2s(sb + SM_A + s * A_TILE_B, Abase + (size_t)at * A_TILE_B, A_TILE_B, fullb);
            bulk_g2s(sb + SM_B + s * B_TILE_B, Bbase + (size_t)btile * B_TILE_B, B_TILE_B, fullb);
            mbar_wait(fullb, ph & 1);

            uint64_t ad  = make_desc(sb + SM_A + s * A_TILE_B);
            uint64_t bd0 = make_desc(sb + SM_B + s * B_TILE_B);
            uint64_t bd1 = bd0 + 1024;             // +16384 B: B rows 128..255
            #pragma unroll
            for (int ks = 0; ks < 4; ++ks) {
                uint32_t en = (c > 0 || ks > 0) ? 1u : 0u;
                mma_bf16_ss(tmem,       ad + 2 * ks, bd0 + 2 * ks, idesc, en);
                mma_bf16_ss(tmem + 128, ad + 2 * ks, bd1 + 2 * ks, idesc, en);
            }
            tc_commit(sb + SM_DONE + 8 * s);
        }
        // drain by the ONE thread with correct phase history (12 completions/stage;
        // in-loop waits consumed through #11; parity 1 selects completion #12).
        mbar_wait(sb + SM_DONE + 0, 1);
        mbar_wait(sb + SM_DONE + 8, 1);
    }
    __syncthreads();          // releases the other 127 threads only after drain
    TC_FENCE_AFTER();

    int lane = tid & 31, w = tid >> 5;
    size_t orow = (size_t)(rowBase + w * 32 + lane) * C3 + colBase;
    const float* bsm = (const float*)(smem + SM_BIAS);
    for (int b = 0; b < 8; ++b) {
        uint32_t r[32];
        LDTM_X32(r, tmem + b * 32);
        TC_WAIT_LD();
        #pragma unroll
        for (int j = 0; j < 32; j += 4) {
            float4 o;
            o.x = __uint_as_float(r[j + 0]) + bsm[b * 32 + j + 0];
            o.y = __uint_as_float(r[j + 1]) + bsm[b * 32 + j + 1];
            o.z = __uint_as_float(r[j + 2]) + bsm[b * 32 + j + 2];
            o.w = __uint_as_float(r[j + 3]) + bsm[b * 32 + j + 3];
            *(float4*)(g_qkv + orow + b * 32 + j) = o;
        }
    }
    TC_FENCE_BEFORE();
    __syncthreads();
    if (tid == 0) {
        mbar_inval(sb + SM_FULL); mbar_inval(sb + SM_FULL + 8);
        mbar_inval(sb + SM_DONE); mbar_inval(sb + SM_DONE + 8);
    }
    __syncthreads();
    if (tid < 32) TC_DEALLOC(tmem, 256);
#else
    // Fallback for the compute_103 PTX pass (never executed on GB300).
    int tid = threadIdx.x;
    int bn = blockIdx.x, bm = blockIdx.y;
    int rowBase = bm * TM, colBase = bn * TN;
    int bt = rowBase / NTOK;
    for (int e = tid; e < TM * TN; e += 128) {
        int i = e / TN, j = e % TN;
        float s = 0.f;
        for (int kk = 0; kk < NCHUNK * TK; ++kk) {
            int c = kk >> 6, col = kk & 63;
            int at = c & 15;
            int btile = (c < 8) ? c : (c - 8);
            uint32_t ao = (uint32_t)i * 128 + col * 2; ao ^= ((ao >> 3) & 0x70);
            uint32_t bo = (uint32_t)j * 128 + col * 2; bo ^= ((bo >> 3) & 0x70);
            float a = __bfloat162float(*(const __nv_bfloat16*)((const char*)g_At + ((size_t)(bm * 16 + at)) * A_TILE_B + ao));
            float b = __bfloat162float(*(const __nv_bfloat16*)((const char*)g_Bt + ((size_t)(bn * 16 + btile)) * B_TILE_B + bo));
            s += a * b;
        }
        g_qkv[(size_t)(rowBase + i) * C3 + colBase + j] = s + g_bias[bt * C3 + colBase + j];
    }
#endif
}

// ---------------- K7: kv = phi(k)^T v, ksum ----------------
__global__ __launch_bounds__(256) void k7_kv() {
    int bt = blockIdx.x, h = blockIdx.y;
    int t = threadIdx.x;
    int d = t >> 2;
    int esub = t & 3;
    __shared__ float ks[16][DH], vs[16][DH];
    float accKV[16];
    #pragma unroll
    for (int j = 0; j < 16; ++j) accKV[j] = 0.f;
    float accS = 0.f;

    const float* base = g_qkv + (size_t)(bt * NTOK) * C3 + h * DH;
    int lrow = t >> 4;
    int lc4  = (t & 15) * 4;

    for (int n0 = 0; n0 < NTOK; n0 += 16) {
        const float* kp = base + (size_t)(n0 + lrow) * C3 + C_ + lc4;
        float4 k4 = *(const float4*)kp;
        ks[lrow][lc4 + 0] = phi(k4.x);
        ks[lrow][lc4 + 1] = phi(k4.y);
        ks[lrow][lc4 + 2] = phi(k4.z);
        ks[lrow][lc4 + 3] = phi(k4.w);
        const float* vp = base + (size_t)(n0 + lrow) * C3 + 2 * C_ + lc4;
        *(float4*)(&vs[lrow][lc4]) = *(const float4*)vp;
        __syncthreads();
        #pragma unroll
        for (int r = 0; r < 16; ++r) {
            float pk = ks[r][d];
            #pragma unroll
            for (int j = 0; j < 16; ++j)
                accKV[j] += pk * vs[r][esub + 4 * j];
            accS += pk;
        }
        __syncthreads();
    }
    float* kvout = g_kv + ((size_t)(bt * NH + h) * DH + d) * DH;
    #pragma unroll
    for (int j = 0; j < 16; ++j) kvout[esub + 4 * j] = accKV[j];
    if (esub == 0) g_ksum[(bt * NH + h) * DH + d] = accS;
}

// ---------------- K8: out = z * (phi(q)*mw) @ kv ----------------
__global__ __launch_bounds__(256) void k8_apply(const float* __restrict__ motion,
                                                float* __restrict__ out) {
    int bt = blockIdx.x, h = blockIdx.y, chunk = blockIdx.z;
    int t = threadIdx.x;
    int sub = t >> 6, e = t & 63;
    __shared__ float kvs[DH * DH];
    __shared__ float ks[DH];
    __shared__ float qs[4][DH];
    __shared__ float mws[4];

    const float* kvg = g_kv + (size_t)(bt * NH + h) * DH * DH;
    for (int i = t; i < DH * DH; i += 256) kvs[i] = kvg[i];
    if (t < DH) ks[t] = g_ksum[(bt * NH + h) * DH + t];
    __syncthreads();

    int n0 = chunk * 96;
    for (int g = 0; g < 96; g += 4) {
        int n = n0 + g + sub;
        float qv = g_qkv[(size_t)(bt * NTOK + n) * C3 + h * DH + e];
        if (e == 0) mws[sub] = 1.f + tanhf(motion[bt * NTOK + n]);
        qs[sub][e] = qv;
        __syncthreads();
        float mw = mws[sub];
        qs[sub][e] = phi(qv) * mw;
        __syncthreads();
        float den = 0.f, o = 0.f;
        #pragma unroll
        for (int d = 0; d < DH; ++d) {
            float qd = qs[sub][d];
            den += qd * ks[d];
            o   += qd * kvs[d * DH + e];
        }
        float z = 1.f / (den + EPS);
        out[(size_t)(bt * NTOK + n) * C_ + h * DH + e] = o * z;
        __syncthreads();
    }
}

// ---------------- launch ----------------
extern "C" void kernel_launch(void* const* d_in, const int* in_sizes, int n_in,
                              void* d_out, int out_size) {
    const float* x      = (const float*)d_in[0];
    const float* motion = (const float*)d_in[1];
    const float* W      = (const float*)d_in[2];
    const float* temb   = (const float*)d_in[3];
    float* out = (float*)d_out;

    cudaFuncSetAttribute(k6_mma, cudaFuncAttributeMaxDynamicSharedMemorySize, SM_SZ);

    kA_split<<<(int)(((size_t)M_ * 128) / 256), 256>>>(x);
    kB_build<<<dim3(C3 / 256, C_), 256>>>(W);
    k1_partial<<<dim3(BT, 8), 512>>>(x, motion);
    k2_final<<<BT, 512>>>(temb);
    k3_vecmat<<<dim3(BT, 6), 256>>>(W, 0);
    k4_temporal<<<dim3(B_, NH), 64>>>();
    k5_prep<<<BT, 512>>>(temb);
    k3_vecmat<<<dim3(BT, 6), 256>>>(W, 1);
    k6_mma<<<dim3(NBN, NBM), 128, SM_SZ>>>();
    k7_kv<<<dim3(BT, NH), 256>>>();
    k8_apply<<<dim3(BT, NH, NTOK / 96), 256>>>(motion, out);
}

// round 6
// speedup vs baseline: 2.4554x; 1.2395x over previous
#include <cuda_runtime.h>
#include <cuda_bf16.h>
#include <math.h>
#include <stdint.h>

#define B_   2
#define T_   16
#define BT   32
#define NTOK 2304
#define C_   512
#define C3   1536
#define NH   8
#define DH   64
#define EPS  1e-6f

#define M_   (BT * NTOK)   // 73728
#define TM   128
#define TN   256
#define TK   64
#define NCHUNK 24          // K' = 1536 = 24 * 64
#define NBM   (M_ / TM)    // 576
#define NBN   (C3 / TN)    // 6
#define A_TILE_B 16384
#define B_TILE_B 32768
#define STAGES 4
#define STG_B  (A_TILE_B + B_TILE_B)   // 49152

#if defined(__CUDA_ARCH_FEAT_SM103_ALL) || defined(__CUDA_ARCH_FEAT_SM100_ALL) || \
    (defined(__CUDA_ARCH_SPECIFIC__) && (__CUDA_ARCH_SPECIFIC__ == 1030))
#define HAS_TCGEN05 1
#else
#define HAS_TCGEN05 0
#endif

// ---------------- scratch ----------------
__device__ float g_qkv[(size_t)BT * NTOK * C3];
__device__ __nv_bfloat16 g_At[(size_t)NBM * 16 * (A_TILE_B / 2)];  // [bm][tile 0-7 hi, 8-15 lo]
__device__ __nv_bfloat16 g_Bt[(size_t)NBN * 16 * (B_TILE_B / 2)];  // [bn][tile 0-7 hi, 8-15 lo]
__device__ float g_part[BT * 8 * C_];
__device__ float g_partmm[BT * 8];
__device__ float g_xtime[BT * C_];
__device__ float g_mm[BT];
__device__ float g_qkvt[BT * C3];
__device__ float g_tout[BT * C_];
__device__ float g_bias[BT * C3];
__device__ float g_kv[BT * NH * DH * DH];
__device__ float g_ksum[BT * NH * DH];

__device__ __forceinline__ float phi(float x) {
    return x > 0.f ? x + 1.f : expf(x);
}

// ---------------- ptx helpers (generic) ----------------
__device__ __forceinline__ uint32_t smem_u32(const void* p) {
    uint32_t a;
    asm("{ .reg .u64 t; cvta.to.shared.u64 t, %1; cvt.u32.u64 %0, t; }" : "=r"(a) : "l"(p));
    return a;
}
static __device__ __forceinline__ uint64_t make_desc(uint32_t addr) {
    const uint64_t base = (uint64_t(2) << 61) | (uint64_t(1) << 46) | (uint64_t(64) << 32) | (uint64_t(1) << 16);
    return base | ((uint64_t)(addr >> 4) & 0x3FFF);
}
__device__ __forceinline__ void mbar_init(uint32_t a, uint32_t cnt) {
    asm volatile("mbarrier.init.shared.b64 [%0], %1;" :: "r"(a), "r"(cnt) : "memory");
}
__device__ __forceinline__ void mbar_inval(uint32_t a) {
    asm volatile("mbarrier.inval.shared.b64 [%0];" :: "r"(a) : "memory");
}
__device__ __forceinline__ void mbar_wait(uint32_t a, uint32_t parity) {
    asm volatile(
        "{\n\t.reg .pred P1;\n\tWL_%=:\n\t"
        "mbarrier.try_wait.parity.acquire.cta.shared::cta.b64 P1, [%0], %1, 0x989680;\n\t"
        "@P1 bra.uni WD_%=;\n\tbra.uni WL_%=;\n\tWD_%=:\n\t}"
        :: "r"(a), "r"(parity) : "memory");
}
__device__ __forceinline__ void mbar_expect_tx(uint32_t a, uint32_t bytes) {
    asm volatile("mbarrier.arrive.expect_tx.shared.b64 _, [%0], %1;"
                 :: "r"(a), "r"(bytes) : "memory");
}
__device__ __forceinline__ void bulk_g2s(uint32_t dst, const void* src, uint32_t bytes, uint32_t mbar) {
    asm volatile("cp.async.bulk.shared::cta.global.mbarrier::complete_tx::bytes [%0], [%1], %2, [%3];"
                 :: "r"(dst), "l"(src), "r"(bytes), "r"(mbar) : "memory");
}

#if HAS_TCGEN05
__device__ __forceinline__ void mma_bf16_ss(uint32_t d, uint64_t ad, uint64_t bd, uint32_t idesc, uint32_t en) {
    asm volatile(
        "{\n\t.reg .pred p;\n\tsetp.ne.u32 p, %4, 0;\n\t"
        "tcgen05.mma.cta_group::1.kind::f16 [%0], %1, %2, %3, {%5, %5, %5, %5}, p;\n\t}"
        :: "r"(d), "l"(ad), "l"(bd), "r"(idesc), "r"(en), "r"(0u) : "memory");
}
__device__ __forceinline__ void tc_commit(uint32_t mbar) {
    asm volatile("tcgen05.commit.cta_group::1.mbarrier::arrive::one.shared::cluster.b64 [%0];"
                 :: "r"(mbar) : "memory");
}
#define TC_ALLOC(sa, n)  asm volatile("tcgen05.alloc.cta_group::1.sync.aligned.shared::cta.b32 [%0], %1;" :: "r"(sa), "r"(n) : "memory")
#define TC_DEALLOC(t, n) asm volatile("tcgen05.dealloc.cta_group::1.sync.aligned.b32 %0, %1;" :: "r"(t), "r"(n))
#define TC_FENCE_AFTER()  asm volatile("tcgen05.fence::after_thread_sync;" ::: "memory")
#define TC_FENCE_BEFORE() asm volatile("tcgen05.fence::before_thread_sync;" ::: "memory")
#define TC_WAIT_LD() asm volatile("tcgen05.wait::ld.sync.aligned;" ::: "memory")
#define LDTM_X32(r, a) \
    asm volatile("tcgen05.ld.sync.aligned.32x32b.x32.b32 " \
        "{%0, %1, %2, %3, %4, %5, %6, %7, %8, %9, %10, %11, %12, %13, %14, %15, " \
        "%16, %17, %18, %19, %20, %21, %22, %23, %24, %25, %26, %27, %28, %29, %30, %31}, [%32];" \
        : "=r"((r)[0]), "=r"((r)[1]), "=r"((r)[2]), "=r"((r)[3]), "=r"((r)[4]), "=r"((r)[5]), "=r"((r)[6]), "=r"((r)[7]), \
          "=r"((r)[8]), "=r"((r)[9]), "=r"((r)[10]), "=r"((r)[11]), "=r"((r)[12]), "=r"((r)[13]), "=r"((r)[14]), "=r"((r)[15]), \
          "=r"((r)[16]), "=r"((r)[17]), "=r"((r)[18]), "=r"((r)[19]), "=r"((r)[20]), "=r"((r)[21]), "=r"((r)[22]), "=r"((r)[23]), \
          "=r"((r)[24]), "=r"((r)[25]), "=r"((r)[26]), "=r"((r)[27]), "=r"((r)[28]), "=r"((r)[29]), "=r"((r)[30]), "=r"((r)[31]) \
        : "r"(a))
#endif

// ---------------- K1: partial frame sums ----------------
__global__ void k1_partial(const float* __restrict__ x, const float* __restrict__ motion) {
    int bt = blockIdx.x, chunk = blockIdx.y;
    int c = threadIdx.x;
    const int RPC = NTOK / 8;
    int n0 = chunk * RPC;
    const float* xp = x + ((size_t)(bt * NTOK + n0)) * C_ + c;
    float s = 0.f;
    for (int r = 0; r < RPC; ++r) s += xp[(size_t)r * C_];
    g_part[(bt * 8 + chunk) * C_ + c] = s;

    __shared__ float sm[512];
    float m = 0.f;
    for (int r = c; r < RPC; r += 512) m += motion[bt * NTOK + n0 + r];
    sm[c] = m;
    __syncthreads();
    for (int off = 256; off > 0; off >>= 1) {
        if (c < off) sm[c] += sm[c + off];
        __syncthreads();
    }
    if (c == 0) g_partmm[bt * 8 + chunk] = sm[0];
}

// ---------------- K2 ----------------
__global__ void k2_final(const float* __restrict__ temb) {
    int bt = blockIdx.x, c = threadIdx.x;
    float s = 0.f;
    for (int j = 0; j < 8; ++j) s += g_part[(bt * 8 + j) * C_ + c];
    g_xtime[bt * C_ + c] = s * (1.f / NTOK) + temb[c];
    if (c == 0) {
        float m = 0.f;
        for (int j = 0; j < 8; ++j) m += g_partmm[bt * 8 + j];
        g_mm[bt] = m * (1.f / NTOK);
    }
}

// ---------------- K3: small vec-mat ----------------
__global__ void k3_vecmat(const float* __restrict__ W, int mode) {
    int bt = blockIdx.x;
    int col = blockIdx.y * 256 + threadIdx.x;
    __shared__ float v[C_];
    for (int i = threadIdx.x; i < C_; i += 256) v[i] = g_xtime[bt * C_ + i];
    __syncthreads();
    float s = 0.f;
    #pragma unroll 8
    for (int c = 0; c < C_; ++c) s += v[c] * W[(size_t)c * C3 + col];
    float* dst = mode ? g_bias : g_qkvt;
    dst[bt * C3 + col] = s;
}

// ---------------- K4: temporal linear attention ----------------
__global__ void k4_temporal() {
    int b = blockIdx.x, h = blockIdx.y, e = threadIdx.x;
    __shared__ float q[T_][DH], k[T_][DH], v[T_][DH];
    __shared__ float kvs[DH][DH + 1], ks[DH], mw[T_];
    for (int t = 0; t < T_; ++t) {
        int base = (b * T_ + t) * C3 + h * DH + e;
        q[t][e] = g_qkvt[base];
        k[t][e] = g_qkvt[base + C_];
        v[t][e] = g_qkvt[base + 2 * C_];
    }
    if (e < T_) mw[e] = 1.f + tanhf(g_mm[b * T_ + e]);
    __syncthreads();
    for (int t = 0; t < T_; ++t) {
        q[t][e] = phi(q[t][e]) * mw[t];
        k[t][e] = phi(k[t][e]);
    }
    __syncthreads();
    {
        float s = 0.f;
        for (int t = 0; t < T_; ++t) s += k[t][e];
        ks[e] = s;
    }
    for (int d = 0; d < DH; ++d) {
        float s = 0.f;
        for (int t = 0; t < T_; ++t) s += k[t][d] * v[t][e];
        kvs[d][e] = s;
    }
    __syncthreads();
    for (int t = 0; t < T_; ++t) {
        float den = 0.f, o = 0.f;
        #pragma unroll
        for (int d = 0; d < DH; ++d) {
            float qd = q[t][d];
            den += qd * ks[d];
            o   += qd * kvs[d][e];
        }
        float z = 1.f / (den + EPS);
        g_tout[(b * T_ + t) * C_ + h * DH + e] = o * z;
    }
}

// ---------------- K5 prep ----------------
__global__ void k5_prep(const float* __restrict__ temb) {
    int bt = blockIdx.x, c = threadIdx.x;
    g_xtime[bt * C_ + c] = temb[c] + g_tout[bt * C_ + c];
}

// ---------------- KA: pre-swizzled tile-contiguous split-A ----------------
__global__ void kA_split(const float* __restrict__ x) {
    size_t idx = (size_t)blockIdx.x * 256 + threadIdx.x;
    size_t row = idx >> 7;
    int q = (int)(idx & 127);
    float4 v = *(const float4*)(x + (row << 9) + q * 4);
    float f[4] = {v.x, v.y, v.z, v.w};
    uint32_t ph[2], pl[2];
    #pragma unroll
    for (int p = 0; p < 2; ++p) {
        __nv_bfloat16 h0 = __float2bfloat16_rn(f[2 * p]);
        __nv_bfloat16 h1 = __float2bfloat16_rn(f[2 * p + 1]);
        __nv_bfloat16 l0 = __float2bfloat16_rn(f[2 * p] - __bfloat162float(h0));
        __nv_bfloat16 l1 = __float2bfloat16_rn(f[2 * p + 1] - __bfloat162float(h1));
        ph[p] = (uint32_t)__bfloat16_as_ushort(h0) | ((uint32_t)__bfloat16_as_ushort(h1) << 16);
        pl[p] = (uint32_t)__bfloat16_as_ushort(l0) | ((uint32_t)__bfloat16_as_ushort(l1) << 16);
    }
    uint2 hv = {ph[0], ph[1]}, lv = {pl[0], pl[1]};

    int bm = (int)(row >> 7);
    int lr = (int)(row & 127);
    int ch = q >> 4;
    uint32_t off = (uint32_t)lr * 128 + (uint32_t)(q & 15) * 8;
    uint32_t so = off ^ ((off >> 3) & 0x70);
    char* hiDst = (char*)g_At + ((size_t)(bm * 16 + ch)) * A_TILE_B + so;
    *(uint2*)hiDst = hv;
    *(uint2*)(hiDst + 8 * A_TILE_B) = lv;
}

// ---------------- KB: pre-swizzled tile-contiguous split-B ----------------
__global__ void kB_build(const float* __restrict__ W) {
    int n = blockIdx.x * 256 + threadIdx.x;
    int k = blockIdx.y;
    float w = W[(size_t)k * C3 + n];
    __nv_bfloat16 hi = __float2bfloat16_rn(w);
    __nv_bfloat16 lo = __float2bfloat16_rn(w - __bfloat162float(hi));
    int bn = n >> 8, rt = n & 255, ch = k >> 6, col = k & 63;
    uint32_t off = (uint32_t)rt * 128 + (uint32_t)col * 2;
    uint32_t so = off ^ ((off >> 3) & 0x70);
    char* dst = (char*)g_Bt + ((size_t)(bn * 16 + ch)) * B_TILE_B + so;
    *(__nv_bfloat16*)dst = hi;
    *(__nv_bfloat16*)(dst + 8 * B_TILE_B) = lo;
}

// ---------------- K6: 4-stage bulk-async-fed tcgen05 bf16 GEMM ----------------
#define SM_BIAS 196608       // after 4 x 48KB stages
#define SM_TPTR 197632
#define SM_FULL 197640       // 4 x 8
#define SM_DONE 197672       // 4 x 8
#define SM_SZ   197704

__global__ void __launch_bounds__(128, 1) k6_mma() {
#if HAS_TCGEN05
    extern __shared__ char smem[];
    uint32_t sb = smem_u32(smem);
    int tid = threadIdx.x;
    int bn = blockIdx.x, bm = blockIdx.y;
    int rowBase = bm * TM, colBase = bn * TN;
    int bt = rowBase / NTOK;

    for (int i = tid; i < TN; i += 128)
        ((float*)(smem + SM_BIAS))[i] = g_bias[bt * C3 + colBase + i];

    if (tid < 32) TC_ALLOC(sb + SM_TPTR, 256);
    if (tid == 0) {
        #pragma unroll
        for (int s = 0; s < STAGES; ++s) {
            mbar_init(sb + SM_FULL + 8 * s, 1);
            mbar_init(sb + SM_DONE + 8 * s, 1);
        }
    }
    __syncthreads();
    uint32_t tmem;
    asm volatile("ld.shared.b32 %0, [%1];" : "=r"(tmem) : "r"(sb + SM_TPTR));

    const uint32_t idesc = (1u << 4) | (1u << 7) | (1u << 10) | (16u << 17) | (8u << 24);

    if (tid == 0) {
        const char* Abase = (const char*)g_At + (size_t)bm * 16 * A_TILE_B;
        const char* Bbase = (const char*)g_Bt + (size_t)bn * 16 * B_TILE_B;

        // prologue: fill stages 0..2 with chunks 0..2 (3 copies in flight)
        #pragma unroll
        for (int p = 0; p < 3; ++p) {
            int at = p, btile = p;
            uint32_t fullb = sb + SM_FULL + 8 * p;
            mbar_expect_tx(fullb, STG_B);
            bulk_g2s(sb + (uint32_t)p * STG_B, Abase + (size_t)at * A_TILE_B, A_TILE_B, fullb);
            bulk_g2s(sb + (uint32_t)p * STG_B + A_TILE_B, Bbase + (size_t)btile * B_TILE_B, B_TILE_B, fullb);
        }

        for (int c = 0; c < NCHUNK; ++c) {
            int s = c & 3;
            mbar_wait(sb + SM_FULL + 8 * s, (c >> 2) & 1);

            uint64_t ad  = make_desc(sb + (uint32_t)s * STG_B);
            uint64_t bd0 = make_desc(sb + (uint32_t)s * STG_B + A_TILE_B);
            uint64_t bd1 = bd0 + 1024;             // +16384 B: B rows 128..255
            #pragma unroll
            for (int ks = 0; ks < 4; ++ks) {
                uint32_t en = (c > 0 || ks > 0) ? 1u : 0u;
                mma_bf16_ss(tmem,       ad + 2 * ks, bd0 + 2 * ks, idesc, en);
                mma_bf16_ss(tmem + 128, ad + 2 * ks, bd1 + 2 * ks, idesc, en);
            }
            tc_commit(sb + SM_DONE + 8 * s);

            int pf = c + 3;
            if (pf < NCHUNK) {
                int sp = pf & 3;
                if (pf >= STAGES) mbar_wait(sb + SM_DONE + 8 * sp, ((pf - 4) >> 2) & 1);
                int at = pf & 15;                     // A: 0-7 hi, 8-15 lo, then hi
                int btile = (pf < 8) ? pf : (pf - 8); // B: hi, hi, lo
                uint32_t fullb = sb + SM_FULL + 8 * sp;
                mbar_expect_tx(fullb, STG_B);
                bulk_g2s(sb + (uint32_t)sp * STG_B, Abase + (size_t)at * A_TILE_B, A_TILE_B, fullb);
                bulk_g2s(sb + (uint32_t)sp * STG_B + A_TILE_B, Bbase + (size_t)btile * B_TILE_B, B_TILE_B, fullb);
            }
        }
        // drain: chunk 23's commit (6th completion on DONE[3]) tracks ALL prior MMAs
        mbar_wait(sb + SM_DONE + 8 * 3, 1);
    }
    __syncthreads();          // release the other 127 threads only after drain
    TC_FENCE_AFTER();

    int lane = tid & 31, w = tid >> 5;
    size_t orow = (size_t)(rowBase + w * 32 + lane) * C3 + colBase;
    const float* bsm = (const float*)(smem + SM_BIAS);
    for (int b = 0; b < 8; ++b) {
        uint32_t r[32];
        LDTM_X32(r, tmem + b * 32);
        TC_WAIT_LD();
        #pragma unroll
        for (int j = 0; j < 32; j += 4) {
            float4 o;
            o.x = __uint_as_float(r[j + 0]) + bsm[b * 32 + j + 0];
            o.y = __uint_as_float(r[j + 1]) + bsm[b * 32 + j + 1];
            o.z = __uint_as_float(r[j + 2]) + bsm[b * 32 + j + 2];
            o.w = __uint_as_float(r[j + 3]) + bsm[b * 32 + j + 3];
            *(float4*)(g_qkv + orow + b * 32 + j) = o;
        }
    }
    TC_FENCE_BEFORE();
    __syncthreads();
    if (tid == 0) {
        #pragma unroll
        for (int s = 0; s < STAGES; ++s) {
            mbar_inval(sb + SM_FULL + 8 * s);
            mbar_inval(sb + SM_DONE + 8 * s);
        }
    }
    __syncthreads();
    if (tid < 32) TC_DEALLOC(tmem, 256);
#else
    // Fallback for the compute_103 PTX pass (never executed on GB300).
    int tid = threadIdx.x;
    int bn = blockIdx.x, bm = blockIdx.y;
    int rowBase = bm * TM, colBase = bn * TN;
    int bt = rowBase / NTOK;
    for (int e = tid; e < TM * TN; e += 128) {
        int i = e / TN, j = e % TN;
        float s = 0.f;
        for (int kk = 0; kk < NCHUNK * TK; ++kk) {
            int c = kk >> 6, col = kk & 63;
            int at = c & 15;
            int btile = (c < 8) ? c : (c - 8);
            uint32_t ao = (uint32_t)i * 128 + col * 2; ao ^= ((ao >> 3) & 0x70);
            uint32_t bo = (uint32_t)j * 128 + col * 2; bo ^= ((bo >> 3) & 0x70);
            float a = __bfloat162float(*(const __nv_bfloat16*)((const char*)g_At + ((size_t)(bm * 16 + at)) * A_TILE_B + ao));
            float b = __bfloat162float(*(const __nv_bfloat16*)((const char*)g_Bt + ((size_t)(bn * 16 + btile)) * B_TILE_B + bo));
            s += a * b;
        }
        g_qkv[(size_t)(rowBase + i) * C3 + colBase + j] = s + g_bias[bt * C3 + colBase + j];
    }
#endif
}

// ---------------- K7: kv = phi(k)^T v, ksum ----------------
__global__ __launch_bounds__(256) void k7_kv() {
    int bt = blockIdx.x, h = blockIdx.y;
    int t = threadIdx.x;
    int d = t >> 2;
    int esub = t & 3;
    __shared__ float ks[16][DH], vs[16][DH];
    float accKV[16];
    #pragma unroll
    for (int j = 0; j < 16; ++j) accKV[j] = 0.f;
    float accS = 0.f;

    const float* base = g_qkv + (size_t)(bt * NTOK) * C3 + h * DH;
    int lrow = t >> 4;
    int lc4  = (t & 15) * 4;

    for (int n0 = 0; n0 < NTOK; n0 += 16) {
        const float* kp = base + (size_t)(n0 + lrow) * C3 + C_ + lc4;
        float4 k4 = *(const float4*)kp;
        ks[lrow][lc4 + 0] = phi(k4.x);
        ks[lrow][lc4 + 1] = phi(k4.y);
        ks[lrow][lc4 + 2] = phi(k4.z);
        ks[lrow][lc4 + 3] = phi(k4.w);
        const float* vp = base + (size_t)(n0 + lrow) * C3 + 2 * C_ + lc4;
        *(float4*)(&vs[lrow][lc4]) = *(const float4*)vp;
        __syncthreads();
        #pragma unroll
        for (int r = 0; r < 16; ++r) {
            float pk = ks[r][d];
            #pragma unroll
            for (int j = 0; j < 16; ++j)
                accKV[j] += pk * vs[r][esub + 4 * j];
            accS += pk;
        }
        __syncthreads();
    }
    float* kvout = g_kv + ((size_t)(bt * NH + h) * DH + d) * DH;
    #pragma unroll
    for (int j = 0; j < 16; ++j) kvout[esub + 4 * j] = accKV[j];
    if (esub == 0) g_ksum[(bt * NH + h) * DH + d] = accS;
}

// ---------------- K8: out = (phi(q)*mw) @ kv / den, den deduplicated ----------------
__global__ __launch_bounds__(256) void k8_apply(const float* __restrict__ motion,
                                                float* __restrict__ out) {
    int bt = blockIdx.x, h = blockIdx.y, chunk = blockIdx.z;
    int t = threadIdx.x;
    int sub = t >> 6, e = t & 63;
    int lane = t & 31, half = (t >> 5) & 1;
    __shared__ float kvs[DH * DH];
    __shared__ float ks[DH];
    __shared__ float qs[4][DH];
    __shared__ float dpar[4][2];

    const float* kvg = g_kv + (size_t)(bt * NH + h) * DH * DH;
    for (int i = t; i < DH * DH; i += 256) kvs[i] = kvg[i];
    if (t < DH) ks[t] = g_ksum[(bt * NH + h) * DH + t];
    __syncthreads();

    int n0 = chunk * 96;
    for (int g = 0; g < 96; g += 4) {
        int n = n0 + g + sub;
        float raw = g_qkv[(size_t)(bt * NTOK + n) * C3 + h * DH + e];
        float mw = 1.f + tanhf(motion[bt * NTOK + n]);   // broadcast load per token
        float qv = phi(raw) * mw;
        qs[sub][e] = qv;
        float dp = qv * ks[e];
        #pragma unroll
        for (int off = 16; off > 0; off >>= 1)
            dp += __shfl_xor_sync(0xffffffffu, dp, off);
        if (lane == 0) dpar[sub][half] = dp;
        __syncthreads();
        float den = dpar[sub][0] + dpar[sub][1];
        float o = 0.f;
        #pragma unroll
        for (int d = 0; d < DH; ++d)
            o += qs[sub][d] * kvs[d * DH + e];
        out[(size_t)(bt * NTOK + n) * C_ + h * DH + e] = o / (den + EPS);
        __syncthreads();
    }
}

// ---------------- launch ----------------
extern "C" void kernel_launch(void* const* d_in, const int* in_sizes, int n_in,
                              void* d_out, int out_size) {
    const float* x      = (const float*)d_in[0];
    const float* motion = (const float*)d_in[1];
    const float* W      = (const float*)d_in[2];
    const float* temb   = (const float*)d_in[3];
    float* out = (float*)d_out;

    cudaFuncSetAttribute(k6_mma, cudaFuncAttributeMaxDynamicSharedMemorySize, SM_SZ);

    kA_split<<<(int)(((size_t)M_ * 128) / 256), 256>>>(x);
    kB_build<<<dim3(C3 / 256, C_), 256>>>(W);
    k1_partial<<<dim3(BT, 8), 512>>>(x, motion);
    k2_final<<<BT, 512>>>(temb);
    k3_vecmat<<<dim3(BT, 6), 256>>>(W, 0);
    k4_temporal<<<dim3(B_, NH), 64>>>();
    k5_prep<<<BT, 512>>>(temb);
    k3_vecmat<<<dim3(BT, 6), 256>>>(W, 1);
    k6_mma<<<dim3(NBN, NBM), 128, SM_SZ>>>();
    k7_kv<<<dim3(BT, NH), 256>>>();
    k8_apply<<<dim3(BT, NH, NTOK / 96), 256>>>(motion, out);
}

// round 7
// speedup vs baseline: 2.5076x; 1.0213x over previous
#include <cuda_runtime.h>
#include <cuda_bf16.h>
#include <math.h>
#include <stdint.h>

#define B_   2
#define T_   16
#define BT   32
#define NTOK 2304
#define C_   512
#define C3   1536
#define NH   8
#define DH   64
#define EPS  1e-6f

#define M_   (BT * NTOK)   // 73728
#define TM   256
#define TN   256
#define TK   64
#define NCHUNK 24          // K' = 1536 = 24 * 64
#define NBM2  (M_ / TM)    // 288
#define NBN   (C3 / TN)    // 6
#define AT_B  32768        // 256 x 64 bf16 swizzled A tile
#define BT_B  32768        // 256 x 64 bf16 swizzled B tile
#define STAGES 3
#define STG_B  (AT_B + BT_B)   // 65536

#if defined(__CUDA_ARCH_FEAT_SM103_ALL) || defined(__CUDA_ARCH_FEAT_SM100_ALL) || \
    (defined(__CUDA_ARCH_SPECIFIC__) && (__CUDA_ARCH_SPECIFIC__ == 1030))
#define HAS_TCGEN05 1
#else
#define HAS_TCGEN05 0
#endif

// ---------------- scratch ----------------
__device__ float g_qkv[(size_t)BT * NTOK * C3];
__device__ __nv_bfloat16 g_At[(size_t)NBM2 * 16 * (AT_B / 2)];  // [bm2][tile 0-7 hi, 8-15 lo] 256-row tiles
__device__ __nv_bfloat16 g_Bt[(size_t)NBN * 16 * (BT_B / 2)];   // [bn][tile 0-7 hi, 8-15 lo]
__device__ float g_part[BT * 8 * C_];
__device__ float g_partmm[BT * 8];
__device__ float g_xtime[BT * C_];
__device__ float g_mm[BT];
__device__ float g_qkvt[BT * C3];
__device__ float g_tout[BT * C_];
__device__ float g_bias[BT * C3];
__device__ float g_kv[BT * NH * DH * DH];
__device__ float g_ksum[BT * NH * DH];

__device__ __forceinline__ float phi(float x) {
    return x > 0.f ? x + 1.f : expf(x);
}

// ---------------- ptx helpers (generic) ----------------
__device__ __forceinline__ uint32_t smem_u32(const void* p) {
    uint32_t a;
    asm("{ .reg .u64 t; cvta.to.shared.u64 t, %1; cvt.u32.u64 %0, t; }" : "=r"(a) : "l"(p));
    return a;
}
static __device__ __forceinline__ uint64_t make_desc(uint32_t addr) {
    const uint64_t base = (uint64_t(2) << 61) | (uint64_t(1) << 46) | (uint64_t(64) << 32) | (uint64_t(1) << 16);
    return base | ((uint64_t)(addr >> 4) & 0x3FFF);
}
__device__ __forceinline__ void mbar_init(uint32_t a, uint32_t cnt) {
    asm volatile("mbarrier.init.shared.b64 [%0], %1;" :: "r"(a), "r"(cnt) : "memory");
}
__device__ __forceinline__ void mbar_inval(uint32_t a) {
    asm volatile("mbarrier.inval.shared.b64 [%0];" :: "r"(a) : "memory");
}
__device__ __forceinline__ void mbar_wait(uint32_t a, uint32_t parity) {
    asm volatile(
        "{\n\t.reg .pred P1;\n\tWL_%=:\n\t"
        "mbarrier.try_wait.parity.acquire.cta.shared::cta.b64 P1, [%0], %1, 0x989680;\n\t"
        "@P1 bra.uni WD_%=;\n\tbra.uni WL_%=;\n\tWD_%=:\n\t}"
        :: "r"(a), "r"(parity) : "memory");
}
__device__ __forceinline__ void mbar_expect_tx(uint32_t a, uint32_t bytes) {
    asm volatile("mbarrier.arrive.expect_tx.shared.b64 _, [%0], %1;"
                 :: "r"(a), "r"(bytes) : "memory");
}
__device__ __forceinline__ void bulk_g2s(uint32_t dst, const void* src, uint32_t bytes, uint32_t mbar) {
    asm volatile("cp.async.bulk.shared::cta.global.mbarrier::complete_tx::bytes [%0], [%1], %2, [%3];"
                 :: "r"(dst), "l"(src), "r"(bytes), "r"(mbar) : "memory");
}

#if HAS_TCGEN05
__device__ __forceinline__ void mma_bf16_ss(uint32_t d, uint64_t ad, uint64_t bd, uint32_t idesc, uint32_t en) {
    asm volatile(
        "{\n\t.reg .pred p;\n\tsetp.ne.u32 p, %4, 0;\n\t"
        "tcgen05.mma.cta_group::1.kind::f16 [%0], %1, %2, %3, {%5, %5, %5, %5}, p;\n\t}"
        :: "r"(d), "l"(ad), "l"(bd), "r"(idesc), "r"(en), "r"(0u) : "memory");
}
__device__ __forceinline__ void tc_commit(uint32_t mbar) {
    asm volatile("tcgen05.commit.cta_group::1.mbarrier::arrive::one.shared::cluster.b64 [%0];"
                 :: "r"(mbar) : "memory");
}
#define TC_ALLOC(sa, n)  asm volatile("tcgen05.alloc.cta_group::1.sync.aligned.shared::cta.b32 [%0], %1;" :: "r"(sa), "r"(n) : "memory")
#define TC_DEALLOC(t, n) asm volatile("tcgen05.dealloc.cta_group::1.sync.aligned.b32 %0, %1;" :: "r"(t), "r"(n))
#define TC_FENCE_AFTER()  asm volatile("tcgen05.fence::after_thread_sync;" ::: "memory")
#define TC_FENCE_BEFORE() asm volatile("tcgen05.fence::before_thread_sync;" ::: "memory")
#define TC_WAIT_LD() asm volatile("tcgen05.wait::ld.sync.aligned;" ::: "memory")
#define LDTM_X32(r, a) \
    asm volatile("tcgen05.ld.sync.aligned.32x32b.x32.b32 " \
        "{%0, %1, %2, %3, %4, %5, %6, %7, %8, %9, %10, %11, %12, %13, %14, %15, " \
        "%16, %17, %18, %19, %20, %21, %22, %23, %24, %25, %26, %27, %28, %29, %30, %31}, [%32];" \
        : "=r"((r)[0]), "=r"((r)[1]), "=r"((r)[2]), "=r"((r)[3]), "=r"((r)[4]), "=r"((r)[5]), "=r"((r)[6]), "=r"((r)[7]), \
          "=r"((r)[8]), "=r"((r)[9]), "=r"((r)[10]), "=r"((r)[11]), "=r"((r)[12]), "=r"((r)[13]), "=r"((r)[14]), "=r"((r)[15]), \
          "=r"((r)[16]), "=r"((r)[17]), "=r"((r)[18]), "=r"((r)[19]), "=r"((r)[20]), "=r"((r)[21]), "=r"((r)[22]), "=r"((r)[23]), \
          "=r"((r)[24]), "=r"((r)[25]), "=r"((r)[26]), "=r"((r)[27]), "=r"((r)[28]), "=r"((r)[29]), "=r"((r)[30]), "=r"((r)[31]) \
        : "r"(a))
#endif

// ---------------- K1: partial frame sums ----------------
__global__ void k1_partial(const float* __restrict__ x, const float* __restrict__ motion) {
    int bt = blockIdx.x, chunk = blockIdx.y;
    int c = threadIdx.x;
    const int RPC = NTOK / 8;
    int n0 = chunk * RPC;
    const float* xp = x + ((size_t)(bt * NTOK + n0)) * C_ + c;
    float s = 0.f;
    for (int r = 0; r < RPC; ++r) s += xp[(size_t)r * C_];
    g_part[(bt * 8 + chunk) * C_ + c] = s;

    __shared__ float sm[512];
    float m = 0.f;
    for (int r = c; r < RPC; r += 512) m += motion[bt * NTOK + n0 + r];
    sm[c] = m;
    __syncthreads();
    for (int off = 256; off > 0; off >>= 1) {
        if (c < off) sm[c] += sm[c + off];
        __syncthreads();
    }
    if (c == 0) g_partmm[bt * 8 + chunk] = sm[0];
}

// ---------------- K2 ----------------
__global__ void k2_final(const float* __restrict__ temb) {
    int bt = blockIdx.x, c = threadIdx.x;
    float s = 0.f;
    for (int j = 0; j < 8; ++j) s += g_part[(bt * 8 + j) * C_ + c];
    g_xtime[bt * C_ + c] = s * (1.f / NTOK) + temb[c];
    if (c == 0) {
        float m = 0.f;
        for (int j = 0; j < 8; ++j) m += g_partmm[bt * 8 + j];
        g_mm[bt] = m * (1.f / NTOK);
    }
}

// ---------------- K3: small vec-mat ----------------
__global__ void k3_vecmat(const float* __restrict__ W, int mode) {
    int bt = blockIdx.x;
    int col = blockIdx.y * 256 + threadIdx.x;
    __shared__ float v[C_];
    for (int i = threadIdx.x; i < C_; i += 256) v[i] = g_xtime[bt * C_ + i];
    __syncthreads();
    float s = 0.f;
    #pragma unroll 8
    for (int c = 0; c < C_; ++c) s += v[c] * W[(size_t)c * C3 + col];
    float* dst = mode ? g_bias : g_qkvt;
    dst[bt * C3 + col] = s;
}

// ---------------- K4: temporal linear attention ----------------
__global__ void k4_temporal() {
    int b = blockIdx.x, h = blockIdx.y, e = threadIdx.x;
    __shared__ float q[T_][DH], k[T_][DH], v[T_][DH];
    __shared__ float kvs[DH][DH + 1], ks[DH], mw[T_];
    for (int t = 0; t < T_; ++t) {
        int base = (b * T_ + t) * C3 + h * DH + e;
        q[t][e] = g_qkvt[base];
        k[t][e] = g_qkvt[base + C_];
        v[t][e] = g_qkvt[base + 2 * C_];
    }
    if (e < T_) mw[e] = 1.f + tanhf(g_mm[b * T_ + e]);
    __syncthreads();
    for (int t = 0; t < T_; ++t) {
        q[t][e] = phi(q[t][e]) * mw[t];
        k[t][e] = phi(k[t][e]);
    }
    __syncthreads();
    {
        float s = 0.f;
        for (int t = 0; t < T_; ++t) s += k[t][e];
        ks[e] = s;
    }
    for (int d = 0; d < DH; ++d) {
        float s = 0.f;
        for (int t = 0; t < T_; ++t) s += k[t][d] * v[t][e];
        kvs[d][e] = s;
    }
    __syncthreads();
    for (int t = 0; t < T_; ++t) {
        float den = 0.f, o = 0.f;
        #pragma unroll
        for (int d = 0; d < DH; ++d) {
            float qd = q[t][d];
            den += qd * ks[d];
            o   += qd * kvs[d][e];
        }
        float z = 1.f / (den + EPS);
        g_tout[(b * T_ + t) * C_ + h * DH + e] = o * z;
    }
}

// ---------------- K5 prep ----------------
__global__ void k5_prep(const float* __restrict__ temb) {
    int bt = blockIdx.x, c = threadIdx.x;
    g_xtime[bt * C_ + c] = temb[c] + g_tout[bt * C_ + c];
}

// ---------------- KA: pre-swizzled 256-row tile-contiguous split-A ----------------
__global__ void kA_split(const float* __restrict__ x) {
    size_t idx = (size_t)blockIdx.x * 256 + threadIdx.x;
    size_t row = idx >> 7;
    int q = (int)(idx & 127);
    float4 v = *(const float4*)(x + (row << 9) + q * 4);
    float f[4] = {v.x, v.y, v.z, v.w};
    uint32_t ph[2], pl[2];
    #pragma unroll
    for (int p = 0; p < 2; ++p) {
        __nv_bfloat16 h0 = __float2bfloat16_rn(f[2 * p]);
        __nv_bfloat16 h1 = __float2bfloat16_rn(f[2 * p + 1]);
        __nv_bfloat16 l0 = __float2bfloat16_rn(f[2 * p] - __bfloat162float(h0));
        __nv_bfloat16 l1 = __float2bfloat16_rn(f[2 * p + 1] - __bfloat162float(h1));
        ph[p] = (uint32_t)__bfloat16_as_ushort(h0) | ((uint32_t)__bfloat16_as_ushort(h1) << 16);
        pl[p] = (uint32_t)__bfloat16_as_ushort(l0) | ((uint32_t)__bfloat16_as_ushort(l1) << 16);
    }
    uint2 hv = {ph[0], ph[1]}, lv = {pl[0], pl[1]};

    int bm2 = (int)(row >> 8);
    int lr  = (int)(row & 255);
    int ch  = q >> 4;                        // K-chunk 0..7
    uint32_t off = (uint32_t)lr * 128 + (uint32_t)(q & 15) * 8;
    uint32_t so = off ^ ((off >> 3) & 0x70);
    char* hiDst = (char*)g_At + ((size_t)(bm2 * 16 + ch)) * AT_B + so;
    *(uint2*)hiDst = hv;
    *(uint2*)(hiDst + 8 * AT_B) = lv;        // lo tiles 8..15
}

// ---------------- KB: pre-swizzled tile-contiguous split-B ----------------
__global__ void kB_build(const float* __restrict__ W) {
    int n = blockIdx.x * 256 + threadIdx.x;
    int k = blockIdx.y;
    float w = W[(size_t)k * C3 + n];
    __nv_bfloat16 hi = __float2bfloat16_rn(w);
    __nv_bfloat16 lo = __float2bfloat16_rn(w - __bfloat162float(hi));
    int bn = n >> 8, rt = n & 255, ch = k >> 6, col = k & 63;
    uint32_t off = (uint32_t)rt * 128 + (uint32_t)col * 2;
    uint32_t so = off ^ ((off >> 3) & 0x70);
    char* dst = (char*)g_Bt + ((size_t)(bn * 16 + ch)) * BT_B + so;
    *(__nv_bfloat16*)dst = hi;
    *(__nv_bfloat16*)(dst + 8 * BT_B) = lo;
}

// ---------------- K6: 3-stage bulk-async tcgen05 bf16 GEMM, 256x256 tile ----------------
#define SM_BIAS 196608       // after 3 x 64KB stages
#define SM_TPTR 197632
#define SM_FULL 197640       // 3 x 8
#define SM_DONE 197664       // 3 x 8
#define SM_SZ   197688

__global__ void __launch_bounds__(128, 1) k6_mma() {
#if HAS_TCGEN05
    extern __shared__ char smem[];
    uint32_t sb = smem_u32(smem);
    int tid = threadIdx.x;
    int bn = blockIdx.x, bm2 = blockIdx.y;
    int rowBase = bm2 * TM, colBase = bn * TN;
    int bt = rowBase / NTOK;                 // 2304 = 9*256: tile within one frame

    for (int i = tid; i < TN; i += 128)
        ((float*)(smem + SM_BIAS))[i] = g_bias[bt * C3 + colBase + i];

    if (tid < 32) TC_ALLOC(sb + SM_TPTR, 512);
    if (tid == 0) {
        #pragma unroll
        for (int s = 0; s < STAGES; ++s) {
            mbar_init(sb + SM_FULL + 8 * s, 1);
            mbar_init(sb + SM_DONE + 8 * s, 1);
        }
    }
    __syncthreads();
    uint32_t tmem;
    asm volatile("ld.shared.b32 %0, [%1];" : "=r"(tmem) : "r"(sb + SM_TPTR));

    const uint32_t idesc = (1u << 4) | (1u << 7) | (1u << 10) | (16u << 17) | (8u << 24); // N=128, M=128

    if (tid == 0) {
        const char* Abase = (const char*)g_At + (size_t)bm2 * 16 * AT_B;
        const char* Bbase = (const char*)g_Bt + (size_t)bn * 16 * BT_B;

        // prologue: fill stages 0..1 with chunks 0..1
        #pragma unroll
        for (int p = 0; p < 2; ++p) {
            uint32_t fullb = sb + SM_FULL + 8 * p;
            mbar_expect_tx(fullb, STG_B);
            bulk_g2s(sb + (uint32_t)p * STG_B,        Abase + (size_t)p * AT_B, AT_B, fullb);
            bulk_g2s(sb + (uint32_t)p * STG_B + AT_B, Bbase + (size_t)p * BT_B, BT_B, fullb);
        }

        for (int c = 0; c < NCHUNK; ++c) {
            int s = c % 3;
            mbar_wait(sb + SM_FULL + 8 * s, (c / 3) & 1);

            uint64_t ad0 = make_desc(sb + (uint32_t)s * STG_B);
            uint64_t ad1 = ad0 + 1024;           // A rows 128..255
            uint64_t bd0 = make_desc(sb + (uint32_t)s * STG_B + AT_B);
            uint64_t bd1 = bd0 + 1024;           // B rows 128..255
            #pragma unroll
            for (int ks = 0; ks < 4; ++ks) {
                uint32_t en = (c > 0 || ks > 0) ? 1u : 0u;
                mma_bf16_ss(tmem,       ad0 + 2 * ks, bd0 + 2 * ks, idesc, en);
                mma_bf16_ss(tmem + 128, ad0 + 2 * ks, bd1 + 2 * ks, idesc, en);
                mma_bf16_ss(tmem + 256, ad1 + 2 * ks, bd0 + 2 * ks, idesc, en);
                mma_bf16_ss(tmem + 384, ad1 + 2 * ks, bd1 + 2 * ks, idesc, en);
            }
            tc_commit(sb + SM_DONE + 8 * s);

            int pf = c + 2;
            if (pf < NCHUNK) {
                int sp = pf % 3;
                if (pf >= 3) mbar_wait(sb + SM_DONE + 8 * sp, ((pf - 3) / 3) & 1);
                int at = pf & 15;                     // A: 0-7 hi, 8-15 lo, then hi
                int btile = (pf < 8) ? pf : (pf - 8); // B: hi, hi, lo
                uint32_t fullb = sb + SM_FULL + 8 * sp;
                mbar_expect_tx(fullb, STG_B);
                bulk_g2s(sb + (uint32_t)sp * STG_B,        Abase + (size_t)at * AT_B, AT_B, fullb);
                bulk_g2s(sb + (uint32_t)sp * STG_B + AT_B, Bbase + (size_t)btile * BT_B, BT_B, fullb);
            }
        }
        // drain: chunk 23's commit (8th completion, use idx 7, on DONE[2]) tracks all prior MMAs
        mbar_wait(sb + SM_DONE + 8 * 2, 1);
    }
    __syncthreads();          // release the other 127 threads only after drain
    TC_FENCE_AFTER();

    int lane = tid & 31, w = tid >> 5;
    const float* bsm = (const float*)(smem + SM_BIAS);
    #pragma unroll
    for (int mh = 0; mh < 2; ++mh) {
        size_t orow = (size_t)(rowBase + mh * 128 + w * 32 + lane) * C3 + colBase;
        #pragma unroll
        for (int nb = 0; nb < 2; ++nb) {
            for (int b = 0; b < 4; ++b) {
                uint32_t r[32];
                LDTM_X32(r, tmem + mh * 256 + nb * 128 + b * 32);
                TC_WAIT_LD();
                int cb = nb * 128 + b * 32;
                #pragma unroll
                for (int j = 0; j < 32; j += 4) {
                    float4 o;
                    o.x = __uint_as_float(r[j + 0]) + bsm[cb + j + 0];
                    o.y = __uint_as_float(r[j + 1]) + bsm[cb + j + 1];
                    o.z = __uint_as_float(r[j + 2]) + bsm[cb + j + 2];
                    o.w = __uint_as_float(r[j + 3]) + bsm[cb + j + 3];
                    *(float4*)(g_qkv + orow + cb + j) = o;
                }
            }
        }
    }
    TC_FENCE_BEFORE();
    __syncthreads();
    if (tid == 0) {
        #pragma unroll
        for (int s = 0; s < STAGES; ++s) {
            mbar_inval(sb + SM_FULL + 8 * s);
            mbar_inval(sb + SM_DONE + 8 * s);
        }
    }
    __syncthreads();
    if (tid < 32) TC_DEALLOC(tmem, 512);
#else
    // Fallback for the compute_103 PTX pass (never executed on GB300).
    int tid = threadIdx.x;
    int bn = blockIdx.x, bm2 = blockIdx.y;
    int rowBase = bm2 * TM, colBase = bn * TN;
    int bt = rowBase / NTOK;
    for (int e = tid; e < TM * TN; e += 128) {
        int i = e / TN, j = e % TN;
        float s = 0.f;
        for (int kk = 0; kk < NCHUNK * TK; ++kk) {
            int c = kk >> 6, col = kk & 63;
            int at = c & 15;
            int btile = (c < 8) ? c : (c - 8);
            uint32_t ao = (uint32_t)i * 128 + col * 2; ao ^= ((ao >> 3) & 0x70);
            uint32_t bo = (uint32_t)j * 128 + col * 2; bo ^= ((bo >> 3) & 0x70);
            float a = __bfloat162float(*(const __nv_bfloat16*)((const char*)g_At + ((size_t)(bm2 * 16 + at)) * AT_B + ao));
            float b = __bfloat162float(*(const __nv_bfloat16*)((const char*)g_Bt + ((size_t)(bn * 16 + btile)) * BT_B + bo));
            s += a * b;
        }
        g_qkv[(size_t)(rowBase + i) * C3 + colBase + j] = s + g_bias[bt * C3 + colBase + j];
    }
#endif
}

// ---------------- K7: kv = phi(k)^T v, ksum ----------------
__global__ __launch_bounds__(256) void k7_kv() {
    int bt = blockIdx.x, h = blockIdx.y;
    int t = threadIdx.x;
    int d = t >> 2;
    int esub = t & 3;
    __shared__ float ks[16][DH], vs[16][DH];
    float accKV[16];
    #pragma unroll
    for (int j = 0; j < 16; ++j) accKV[j] = 0.f;
    float accS = 0.f;

    const float* base = g_qkv + (size_t)(bt * NTOK) * C3 + h * DH;
    int lrow = t >> 4;
    int lc4  = (t & 15) * 4;

    for (int n0 = 0; n0 < NTOK; n0 += 16) {
        const float* kp = base + (size_t)(n0 + lrow) * C3 + C_ + lc4;
        float4 k4 = *(const float4*)kp;
        ks[lrow][lc4 + 0] = phi(k4.x);
        ks[lrow][lc4 + 1] = phi(k4.y);
        ks[lrow][lc4 + 2] = phi(k4.z);
        ks[lrow][lc4 + 3] = phi(k4.w);
        const float* vp = base + (size_t)(n0 + lrow) * C3 + 2 * C_ + lc4;
        *(float4*)(&vs[lrow][lc4]) = *(const float4*)vp;
        __syncthreads();
        #pragma unroll
        for (int r = 0; r < 16; ++r) {
            float pk = ks[r][d];
            #pragma unroll
            for (int j = 0; j < 16; ++j)
                accKV[j] += pk * vs[r][esub + 4 * j];
            accS += pk;
        }
        __syncthreads();
    }
    float* kvout = g_kv + ((size_t)(bt * NH + h) * DH + d) * DH;
    #pragma unroll
    for (int j = 0; j < 16; ++j) kvout[esub + 4 * j] = accKV[j];
    if (esub == 0) g_ksum[(bt * NH + h) * DH + d] = accS;
}

// ---------------- K8: out = (phi(q)*mw) @ kv / den, den deduplicated ----------------
__global__ __launch_bounds__(256) void k8_apply(const float* __restrict__ motion,
                                                float* __restrict__ out) {
    int bt = blockIdx.x, h = blockIdx.y, chunk = blockIdx.z;
    int t = threadIdx.x;
    int sub = t >> 6, e = t & 63;
    int lane = t & 31, half = (t >> 5) & 1;
    __shared__ float kvs[DH * DH];
    __shared__ float ks[DH];
    __shared__ float qs[4][DH];
    __shared__ float dpar[4][2];

    const float* kvg = g_kv + (size_t)(bt * NH + h) * DH * DH;
    for (int i = t; i < DH * DH; i += 256) kvs[i] = kvg[i];
    if (t < DH) ks[t] = g_ksum[(bt * NH + h) * DH + t];
    __syncthreads();

    int n0 = chunk * 96;
    for (int g = 0; g < 96; g += 4) {
        int n = n0 + g + sub;
        float raw = g_qkv[(size_t)(bt * NTOK + n) * C3 + h * DH + e];
        float mw = 1.f + tanhf(motion[bt * NTOK + n]);
        float qv = phi(raw) * mw;
        qs[sub][e] = qv;
        float dp = qv * ks[e];
        #pragma unroll
        for (int off = 16; off > 0; off >>= 1)
            dp += __shfl_xor_sync(0xffffffffu, dp, off);
        if (lane == 0) dpar[sub][half] = dp;
        __syncthreads();
        float den = dpar[sub][0] + dpar[sub][1];
        float o = 0.f;
        #pragma unroll
        for (int d = 0; d < DH; ++d)
            o += qs[sub][d] * kvs[d * DH + e];
        out[(size_t)(bt * NTOK + n) * C_ + h * DH + e] = o / (den + EPS);
        __syncthreads();
    }
}

// ---------------- launch ----------------
extern "C" void kernel_launch(void* const* d_in, const int* in_sizes, int n_in,
                              void* d_out, int out_size) {
    const float* x      = (const float*)d_in[0];
    const float* motion = (const float*)d_in[1];
    const float* W      = (const float*)d_in[2];
    const float* temb   = (const float*)d_in[3];
    float* out = (float*)d_out;

    cudaFuncSetAttribute(k6_mma, cudaFuncAttributeMaxDynamicSharedMemorySize, SM_SZ);

    kA_split<<<(int)(((size_t)M_ * 128) / 256), 256>>>(x);
    kB_build<<<dim3(C3 / 256, C_), 256>>>(W);
    k1_partial<<<dim3(BT, 8), 512>>>(x, motion);
    k2_final<<<BT, 512>>>(temb);
    k3_vecmat<<<dim3(BT, 6), 256>>>(W, 0);
    k4_temporal<<<dim3(B_, NH), 64>>>();
    k5_prep<<<BT, 512>>>(temb);
    k3_vecmat<<<dim3(BT, 6), 256>>>(W, 1);
    k6_mma<<<dim3(NBN, NBM2), 128, SM_SZ>>>();
    k7_kv<<<dim3(BT, NH), 256>>>();
    k8_apply<<<dim3(BT, NH, NTOK / 96), 256>>>(motion, out);
}